// round 12
// baseline (speedup 1.0000x reference)
#include <cuda_runtime.h>
#include <cuda_fp16.h>
#include <cstdint>
#include <math.h>

#define BSZ 4
#define SEQ 2048
#define DIM 512
#define NHEAD 8
#define HD 64
#define ATT_SCALE 0.044194173824159216f        // 1/sqrt(512)
#define EXC (ATT_SCALE * 1.4426950408889634f)  // scale * log2(e)

// ---------------------------------------------------------------------------
// Scratch (static device globals: allocation-free)
// ---------------------------------------------------------------------------
__device__ __half g_M1h[BSZ*SEQ*DIM];
__device__ __half g_M2h[BSZ*SEQ*DIM];
__device__ __half g_Wqt [DIM*DIM];   // transposed [n][k]
__device__ __half g_Wkvt[DIM*DIM];   // transposed [n][k]
__device__ __half g_Qh [BSZ*SEQ*DIM];   // pre-scaled by EXC
__device__ __half g_KVh[BSZ*SEQ*DIM];
__device__ float  g_A  [BSZ*SEQ*DIM];

// ---------------------------------------------------------------------------
// Baseline-PTX helpers (compute_80 features only: mma.sync / ldmatrix / cp.async)
// ---------------------------------------------------------------------------
__device__ __forceinline__ uint32_t smem_u32(const void* p) {
    uint32_t a;
    asm("{ .reg .u64 t; cvta.to.shared.u64 t, %1; cvt.u32.u64 %0, t; }" : "=r"(a) : "l"(p));
    return a;
}
#define SWZ(off) ((off) ^ (((off) >> 3) & 0x70))

#define LDSM_X4(r0,r1,r2,r3,a) \
    asm volatile("ldmatrix.sync.aligned.m8n8.x4.shared.b16 {%0,%1,%2,%3}, [%4];" \
        : "=r"(r0),"=r"(r1),"=r"(r2),"=r"(r3) : "r"(a))
#define LDSM_X4T(r0,r1,r2,r3,a) \
    asm volatile("ldmatrix.sync.aligned.m8n8.x4.trans.shared.b16 {%0,%1,%2,%3}, [%4];" \
        : "=r"(r0),"=r"(r1),"=r"(r2),"=r"(r3) : "r"(a))

__device__ __forceinline__ void mma_f16(float c[4], uint32_t a0, uint32_t a1,
                                        uint32_t a2, uint32_t a3,
                                        uint32_t b0, uint32_t b1) {
    asm volatile(
        "mma.sync.aligned.m16n8k16.row.col.f32.f16.f16.f32 "
        "{%0,%1,%2,%3}, {%4,%5,%6,%7}, {%8,%9}, {%0,%1,%2,%3};"
        : "+f"(c[0]), "+f"(c[1]), "+f"(c[2]), "+f"(c[3])
        : "r"(a0), "r"(a1), "r"(a2), "r"(a3), "r"(b0), "r"(b1));
}

#define CP_ASYNC16(dst, src) \
    asm volatile("cp.async.cg.shared.global [%0], [%1], 16;" :: "r"(dst), "l"(src))
#define CP_COMMIT() asm volatile("cp.async.commit_group;" ::: "memory")
#define CP_WAIT1()  asm volatile("cp.async.wait_group 1;" ::: "memory")
#define CP_WAIT0()  asm volatile("cp.async.wait_group 0;" ::: "memory")

__device__ __forceinline__ uint32_t cvt_h2(float hi, float lo) {
    uint32_t r;
    asm("cvt.rn.f16x2.f32 %0, %1, %2;" : "=r"(r) : "f"(hi), "f"(lo));
    return r;
}
#define EX2_H2(d, a) asm("ex2.approx.f16x2 %0, %1;" : "=r"(d) : "r"(a))

// ldmatrix address builders (row stride 128B, SW128 swizzle) — prologue only
__device__ __forceinline__ uint32_t lm_a(uint32_t base, int lane, int m0, int k0) {
    int mat = lane >> 3, r = lane & 7;
    int row = m0 + r + ((mat & 1) ? 8 : 0);
    int colb = (k0 + ((mat & 2) ? 8 : 0)) * 2;
    uint32_t off = (uint32_t)row * 128u + (uint32_t)colb;
    return base + SWZ(off);
}
__device__ __forceinline__ uint32_t lm_bs(uint32_t base, int lane, int n0, int k0) {
    int mat = lane >> 3, r = lane & 7;
    int row = n0 + r + ((mat & 2) ? 8 : 0);
    int colb = (k0 + ((mat & 1) ? 8 : 0)) * 2;
    uint32_t off = (uint32_t)row * 128u + (uint32_t)colb;
    return base + SWZ(off);
}

// ---------------------------------------------------------------------------
// Convert modal inputs fp32 -> fp16 (elementwise).
// ---------------------------------------------------------------------------
__global__ __launch_bounds__(256) void convert_in(
    const float* __restrict__ m1, const float* __restrict__ m2)
{
    const float* src = blockIdx.y ? m2 : m1;
    __half* dst = blockIdx.y ? g_M2h : g_M1h;
    size_t i4 = ((size_t)blockIdx.x * 256 + threadIdx.x) * 4;
    float4 v = *(const float4*)(src + i4);
    uint2 w = make_uint2(cvt_h2(v.y, v.x), cvt_h2(v.w, v.z));
    *(uint2*)(dst + i4) = w;
}

// ---------------------------------------------------------------------------
// Convert + transpose W (512x512): Wt[n][k] = W[k][n], fp16 out.
// ---------------------------------------------------------------------------
__global__ __launch_bounds__(256) void convert_wt(
    const float* __restrict__ Wq, const float* __restrict__ Wkv)
{
    __shared__ float t[32][33];
    const float* W = blockIdx.z ? Wkv : Wq;
    __half* Wt = blockIdx.z ? g_Wkvt : g_Wqt;
    int k0 = blockIdx.x * 32, n0 = blockIdx.y * 32;
    int tx = threadIdx.x, ty = threadIdx.y;
    #pragma unroll
    for (int i = 0; i < 4; i++)
        t[ty + 8 * i][tx] = W[(size_t)(k0 + ty + 8 * i) * DIM + n0 + tx];
    __syncthreads();
    #pragma unroll
    for (int i = 0; i < 4; i++)
        Wt[(size_t)(n0 + ty + 8 * i) * DIM + k0 + tx] =
            __float2half(t[tx][ty + 8 * i]);
}

// ---------------------------------------------------------------------------
// Tensor-core projection GEMM: C(8192x512) = A @ W + bias, fp16 in/out.
// Q output (blockIdx.z==0) is PRE-SCALED by EXC for the attention softmax.
// ---------------------------------------------------------------------------
#define GSM_A0 0
#define GSM_B0 16384
#define GSM_A1 32768
#define GSM_B1 49152
#define GEMM_SMEM 65536

__global__ __launch_bounds__(256) void gemm_tc(
    const float* __restrict__ bq, const float* __restrict__ bkv)
{
    extern __shared__ char smem[];
    const uint32_t sb = smem_u32(smem);

    const __half* A; const __half* Wt;
    const float* bias; __half* C;
    if (blockIdx.z == 0) { A = g_M1h; Wt = g_Wqt;  bias = bq;  C = g_Qh;  }
    else                 { A = g_M2h; Wt = g_Wkvt; bias = bkv; C = g_KVh; }
    const float escale = (blockIdx.z == 0) ? EXC : 1.0f;

    const int tid = threadIdx.x;
    const int lane = tid & 31, wid = tid >> 5;
    const int g = lane >> 2, tig = lane & 3;
    const int wm = wid & 1, wn = wid >> 1;
    const int m0 = blockIdx.y * 128, n0 = blockIdx.x * 128;

    const int lrow = tid >> 3, lch = tid & 7;

    {
        const __half* As = A  + (size_t)(m0 + lrow) * DIM + lch * 8;
        const __half* Bs = Wt + (size_t)(n0 + lrow) * DIM + lch * 8;
        #pragma unroll
        for (int p = 0; p < 4; p++) {
            uint32_t off = SWZ((uint32_t)(lrow + p * 32) * 128u + (uint32_t)lch * 16u);
            CP_ASYNC16(sb + GSM_A0 + off, As + (size_t)p * 32 * DIM);
            CP_ASYNC16(sb + GSM_B0 + off, Bs + (size_t)p * 32 * DIM);
        }
        CP_COMMIT();
    }

    float acc[4][4][4];
    #pragma unroll
    for (int m = 0; m < 4; m++)
        #pragma unroll
        for (int n = 0; n < 4; n++)
            #pragma unroll
            for (int k = 0; k < 4; k++) acc[m][n][k] = 0.f;

    for (int kt = 0; kt < 8; kt++) {
        const int cur = kt & 1, nxt = cur ^ 1;
        if (kt < 7) {
            const __half* As = A  + (size_t)(m0 + lrow) * DIM + (kt + 1) * 64 + lch * 8;
            const __half* Bs = Wt + (size_t)(n0 + lrow) * DIM + (kt + 1) * 64 + lch * 8;
            const uint32_t ab = sb + (nxt ? GSM_A1 : GSM_A0);
            const uint32_t bb = sb + (nxt ? GSM_B1 : GSM_B0);
            #pragma unroll
            for (int p = 0; p < 4; p++) {
                uint32_t off = SWZ((uint32_t)(lrow + p * 32) * 128u + (uint32_t)lch * 16u);
                CP_ASYNC16(ab + off, As + (size_t)p * 32 * DIM);
                CP_ASYNC16(bb + off, Bs + (size_t)p * 32 * DIM);
            }
            CP_COMMIT();
            CP_WAIT1();
        } else {
            CP_WAIT0();
        }
        __syncthreads();

        const uint32_t abase = sb + (cur ? GSM_A1 : GSM_A0);
        const uint32_t bbase = sb + (cur ? GSM_B1 : GSM_B0);

        #pragma unroll
        for (int kf = 0; kf < 4; kf++) {
            uint32_t qa[4][4];
            #pragma unroll
            for (int m = 0; m < 4; m++)
                LDSM_X4(qa[m][0], qa[m][1], qa[m][2], qa[m][3],
                        lm_a(abase, lane, wm * 64 + m * 16, kf * 16));
            uint32_t bb[2][4];
            #pragma unroll
            for (int np = 0; np < 2; np++)
                LDSM_X4(bb[np][0], bb[np][1], bb[np][2], bb[np][3],
                        lm_bs(bbase, lane, wn * 32 + np * 16, kf * 16));
            #pragma unroll
            for (int m = 0; m < 4; m++)
                #pragma unroll
                for (int np = 0; np < 2; np++)
                    #pragma unroll
                    for (int nt = 0; nt < 2; nt++)
                        mma_f16(acc[m][np * 2 + nt],
                                qa[m][0], qa[m][1], qa[m][2], qa[m][3],
                                bb[np][nt * 2], bb[np][nt * 2 + 1]);
        }
        __syncthreads();
    }

    float2 bf[4];
    #pragma unroll
    for (int n = 0; n < 4; n++)
        bf[n] = *(const float2*)&bias[n0 + wn * 32 + n * 8 + 2 * tig];

    #pragma unroll
    for (int m = 0; m < 4; m++) {
        int row = m0 + wm * 64 + m * 16 + g;
        #pragma unroll
        for (int n = 0; n < 4; n++) {
            int col = n0 + wn * 32 + n * 8 + 2 * tig;
            *(uint32_t*)(C + (size_t)row * DIM + col) =
                cvt_h2((acc[m][n][1] + bf[n].y) * escale,
                       (acc[m][n][0] + bf[n].x) * escale);
            *(uint32_t*)(C + (size_t)(row + 8) * DIM + col) =
                cvt_h2((acc[m][n][3] + bf[n].y) * escale,
                       (acc[m][n][2] + bf[n].x) * escale);
        }
    }
}

// ---------------------------------------------------------------------------
// fp16 mma.sync flash attention.
// 256 threads / 8 warps, CTA = 256 q-rows, 32 q-rows (2 m-tiles) per warp:
// every K fragment a warp loads feeds 2 m-tiles -> smem traffic per q-row
// HALVED vs the 16-row warp tile (smem was co-binding with tensor at L1=62%).
// 1 CTA/SM (regs ~200); Q pre-scaled by EXC; ex2.f16x2 softmax; row sums via
// all-ones tensor column.
// ---------------------------------------------------------------------------
#define QROWS 256
#define SMQ   0
#define SMK0  32768
#define SMM2  65536
#define ATT_SMEM (65536 + 2 * 128 * 4)
#define ONES_H2 0x3C003C00u

__global__ __launch_bounds__(256, 1) void attn_mma(
    const int* __restrict__ um1, const int* __restrict__ um2)
{
    extern __shared__ char smem[];
    const uint32_t sb = smem_u32(smem);
    float* m2f = (float*)(smem + SMM2);

    const int tid = threadIdx.x;
    const int lane = tid & 31, wid = tid >> 5;
    const int g = lane >> 2, tig = lane & 3;
    const int b = blockIdx.z, h = blockIdx.y, qt = blockIdx.x;
    const int mbase = wid * 32;

    // --- prologue: async K tile 0, additive m2 tile 0, plain Q tile (256 rows) ---
    {
        const __half* src = g_KVh + (size_t)(b * SEQ) * DIM + h * HD;
        #pragma unroll
        for (int p = 0; p < 4; p++) {
            int row = (tid >> 3) + p * 32, ch = tid & 7;
            uint32_t dst = sb + SMK0 + SWZ((uint32_t)row * 128u + (uint32_t)ch * 16u);
            CP_ASYNC16(dst, src + (size_t)row * DIM + ch * 8);
        }
        CP_COMMIT();
        if (tid < 128) m2f[tid] = (um2[b * SEQ + tid] != 0) ? 0.0f : -1e30f;

        const __half* qs = g_Qh + (size_t)(b * SEQ + qt * QROWS) * DIM + h * HD;
        #pragma unroll
        for (int p = 0; p < 8; p++) {
            int row = (tid >> 3) + p * 32, ch = tid & 7;
            uint4 v = *(const uint4*)(qs + (size_t)row * DIM + ch * 8);
            *(uint4*)(smem + SMQ + SWZ((uint32_t)row * 128u + (uint32_t)ch * 16u)) = v;
        }
    }

    bool rv[2][2];
    #pragma unroll
    for (int m = 0; m < 2; m++)
        #pragma unroll
        for (int r = 0; r < 2; r++)
            rv[m][r] = um1[b * SEQ + qt * QROWS + mbase + m * 16 + r * 8 + g] != 0;

    // --- precomputed LDSM lane bases (SWZ is affine for 8-multiple rows) ---
    const int matq = lane >> 3, rl = lane & 7;
    const uint32_t rsw = (uint32_t)rl << 4;
    const uint32_t row_bs = (uint32_t)(rl + ((matq & 2) ? 8 : 0)) * 128u;
    const uint32_t cl_bs  = (matq & 1) ? 16u : 0u;
    uint32_t bsk[4];
    #pragma unroll
    for (int kf = 0; kf < 4; kf++)
        bsk[kf] = sb + SMK0 + row_bs + (((uint32_t)kf * 32u + cl_bs) ^ rsw);
    const uint32_t row_bo = (uint32_t)(rl + ((matq & 1) ? 8 : 0)) * 128u;
    const uint32_t cl_bo  = (matq & 2) ? 16u : 0u;
    uint32_t bok[4];
    #pragma unroll
    for (int dp = 0; dp < 4; dp++)
        bok[dp] = sb + SMK0 + row_bo + (((uint32_t)dp * 32u + cl_bo) ^ rsw);

    __syncthreads();   // Q visible

    // Q a-frags (persistent): 2 m-tiles per warp
    uint32_t qa[2][4][4];
    #pragma unroll
    for (int m = 0; m < 2; m++)
        #pragma unroll
        for (int kf = 0; kf < 4; kf++)
            LDSM_X4(qa[m][kf][0], qa[m][kf][1], qa[m][kf][2], qa[m][kf][3],
                    lm_a(sb + SMQ, lane, mbase + m * 16, kf * 16));

    float oc[2][8][4];
    #pragma unroll
    for (int m = 0; m < 2; m++)
        #pragma unroll
        for (int n = 0; n < 8; n++)
            #pragma unroll
            for (int k = 0; k < 4; k++) oc[m][n][k] = 0.f;
    float os[2][4];
    #pragma unroll
    for (int m = 0; m < 2; m++)
        #pragma unroll
        for (int k = 0; k < 4; k++) os[m][k] = 0.f;

    for (int kt = 0; kt < 16; kt++) {
        const int cur = kt & 1, nxt = cur ^ 1;
        if (kt < 15) {
            const __half* src =
                g_KVh + (size_t)(b * SEQ + (kt + 1) * 128) * DIM + h * HD;
            #pragma unroll
            for (int p = 0; p < 4; p++) {
                int row = (tid >> 3) + p * 32, ch = tid & 7;
                uint32_t dst = sb + SMK0 + (uint32_t)nxt * 16384u +
                               SWZ((uint32_t)row * 128u + (uint32_t)ch * 16u);
                CP_ASYNC16(dst, src + (size_t)row * DIM + ch * 8);
            }
            CP_COMMIT();
            if (tid < 128)
                m2f[nxt * 128 + tid] = (um2[b * SEQ + (kt + 1) * 128 + tid] != 0) ? 0.0f : -1e30f;
            CP_WAIT1();
        } else {
            CP_WAIT0();
        }
        __syncthreads();   // K[cur] + m2[cur] ready

        const uint32_t koff = (uint32_t)cur * 16384u;
        uint32_t bsc[4], boc[4];
        #pragma unroll
        for (int i = 0; i < 4; i++) { bsc[i] = bsk[i] + koff; boc[i] = bok[i] + koff; }
        const float* m2c = m2f + cur * 128 + 2 * tig;

        #pragma unroll
        for (int c4 = 0; c4 < 4; c4++) {
            // ---- S chunk: 32 keys x 2 m-tiles ----
            float sc[2][4][4];
            #pragma unroll
            for (int m = 0; m < 2; m++)
                #pragma unroll
                for (int n = 0; n < 4; n++)
                    #pragma unroll
                    for (int k = 0; k < 4; k++) sc[m][n][k] = 0.f;

            #pragma unroll
            for (int np = 0; np < 2; np++) {
                const uint32_t roff = (uint32_t)(c4 * 32 + np * 16) * 128u;
                uint32_t bb[4][4];
                #pragma unroll
                for (int kf = 0; kf < 4; kf++)
                    LDSM_X4(bb[kf][0], bb[kf][1], bb[kf][2], bb[kf][3],
                            bsc[kf] + roff);
                #pragma unroll
                for (int m = 0; m < 2; m++)
                    #pragma unroll
                    for (int nt = 0; nt < 2; nt++)
                        #pragma unroll
                        for (int kf = 0; kf < 4; kf++)
                            mma_f16(sc[m][np * 2 + nt],
                                    qa[m][kf][0], qa[m][kf][1], qa[m][kf][2], qa[m][kf][3],
                                    bb[kf][nt * 2], bb[kf][nt * 2 + 1]);
            }

            // ---- softmax: masked add -> f16x2 pack -> ex2.f16x2 ----
            uint32_t aP[2][2][4];
            #pragma unroll
            for (int m = 0; m < 2; m++) {
                #pragma unroll
                for (int n = 0; n < 4; n++) {
                    float2 mv = *(const float2*)&m2c[c4 * 32 + n * 8];
                    float x0 = sc[m][n][0] + mv.x;
                    float x1 = sc[m][n][1] + mv.y;
                    float x2 = sc[m][n][2] + mv.x;
                    float x3 = sc[m][n][3] + mv.y;
                    x0 = rv[m][0] ? x0 : 0.0f;   // exp2(0)=1 -> uniform row
                    x1 = rv[m][0] ? x1 : 0.0f;
                    x2 = rv[m][1] ? x2 : 0.0f;
                    x3 = rv[m][1] ? x3 : 0.0f;
                    uint32_t plo = cvt_h2(x1, x0);
                    uint32_t phi = cvt_h2(x3, x2);
                    EX2_H2(plo, plo);
                    EX2_H2(phi, phi);
                    aP[m][n >> 1][(n & 1) * 2 + 0] = plo;
                    aP[m][n >> 1][(n & 1) * 2 + 1] = phi;
                }
            }

            // ---- O += P @ K (V = K); B-frags loaded ONCE, feed both m-tiles ----
            #pragma unroll
            for (int kf = 0; kf < 2; kf++) {
                const uint32_t roff = (uint32_t)(c4 * 32 + kf * 16) * 128u;
                #pragma unroll
                for (int m = 0; m < 2; m++)
                    mma_f16(os[m], aP[m][kf][0], aP[m][kf][1],
                            aP[m][kf][2], aP[m][kf][3], ONES_H2, ONES_H2);
                #pragma unroll
                for (int dp = 0; dp < 4; dp++) {
                    uint32_t r0, r1, r2, r3;
                    LDSM_X4T(r0, r1, r2, r3, boc[dp] + roff);
                    #pragma unroll
                    for (int m = 0; m < 2; m++) {
                        mma_f16(oc[m][dp * 2],
                                aP[m][kf][0], aP[m][kf][1], aP[m][kf][2], aP[m][kf][3],
                                r0, r1);
                        mma_f16(oc[m][dp * 2 + 1],
                                aP[m][kf][0], aP[m][kf][1], aP[m][kf][2], aP[m][kf][3],
                                r2, r3);
                    }
                }
            }
        }
        __syncthreads();   // done reading K[cur] before overwrite
    }

    // ---- finalize: row sums in os[m][0] (row g) and os[m][2] (row g+8) ----
    float* Og = g_A + (size_t)(b * SEQ + qt * QROWS) * DIM + h * HD;
    #pragma unroll
    for (int m = 0; m < 2; m++) {
        const float inv0 = 1.0f / os[m][0];
        const float inv1 = 1.0f / os[m][2];
        int row0 = mbase + m * 16 + g;
        #pragma unroll
        for (int dt = 0; dt < 8; dt++) {
            int col = dt * 8 + 2 * tig;
            *(float2*)(Og + (size_t)row0 * DIM + col) =
                make_float2(oc[m][dt][0] * inv0, oc[m][dt][1] * inv0);
            *(float2*)(Og + (size_t)(row0 + 8) * DIM + col) =
                make_float2(oc[m][dt][2] * inv1, oc[m][dt][3] * inv1);
        }
    }
}

// ---------------------------------------------------------------------------
// Epilogue: x = LN1(attn + modal1); out = LN2(attn + x).  (FFN is dead code.)
// ---------------------------------------------------------------------------
__global__ __launch_bounds__(128) void epilogue_kernel(
    const float* __restrict__ modal1,
    const float* __restrict__ g1, const float* __restrict__ b1,
    const float* __restrict__ g2, const float* __restrict__ b2,
    float* __restrict__ out)
{
    __shared__ float red[2][4];
    const int row = blockIdx.x;
    const int t = threadIdx.x;
    const int lane = t & 31, wid = t >> 5;

    const float4 av = ((const float4*)(g_A    + (size_t)row * DIM))[t];
    const float4 mv = ((const float4*)(modal1 + (size_t)row * DIM))[t];
    float x[4] = {av.x + mv.x, av.y + mv.y, av.z + mv.z, av.w + mv.w};

    float s = x[0] + x[1] + x[2] + x[3];
    float q = x[0]*x[0] + x[1]*x[1] + x[2]*x[2] + x[3]*x[3];
    #pragma unroll
    for (int off = 16; off > 0; off >>= 1) {
        s += __shfl_xor_sync(0xffffffffu, s, off);
        q += __shfl_xor_sync(0xffffffffu, q, off);
    }
    if (lane == 0) { red[0][wid] = s; red[1][wid] = q; }
    __syncthreads();
    s = red[0][0] + red[0][1] + red[0][2] + red[0][3];
    q = red[1][0] + red[1][1] + red[1][2] + red[1][3];
    float mean = s * (1.0f / 512.0f);
    float var  = q * (1.0f / 512.0f) - mean * mean;
    float rstd = rsqrtf(var + 1e-5f);

    const float4 g1f = ((const float4*)g1)[t];
    const float4 b1f = ((const float4*)b1)[t];
    float y[4];
    y[0] = av.x + ((x[0] - mean) * rstd * g1f.x + b1f.x);
    y[1] = av.y + ((x[1] - mean) * rstd * g1f.y + b1f.y);
    y[2] = av.z + ((x[2] - mean) * rstd * g1f.z + b1f.z);
    y[3] = av.w + ((x[3] - mean) * rstd * g1f.w + b1f.w);

    __syncthreads();
    s = y[0] + y[1] + y[2] + y[3];
    q = y[0]*y[0] + y[1]*y[1] + y[2]*y[2] + y[3]*y[3];
    #pragma unroll
    for (int off = 16; off > 0; off >>= 1) {
        s += __shfl_xor_sync(0xffffffffu, s, off);
        q += __shfl_xor_sync(0xffffffffu, q, off);
    }
    if (lane == 0) { red[0][wid] = s; red[1][wid] = q; }
    __syncthreads();
    s = red[0][0] + red[0][1] + red[0][2] + red[0][3];
    q = red[1][0] + red[1][1] + red[1][2] + red[1][3];
    float mean2 = s * (1.0f / 512.0f);
    float var2  = q * (1.0f / 512.0f) - mean2 * mean2;
    float rstd2 = rsqrtf(var2 + 1e-5f);

    const float4 g2f = ((const float4*)g2)[t];
    const float4 b2f = ((const float4*)b2)[t];
    float4 ov = make_float4((y[0] - mean2) * rstd2 * g2f.x + b2f.x,
                            (y[1] - mean2) * rstd2 * g2f.y + b2f.y,
                            (y[2] - mean2) * rstd2 * g2f.z + b2f.z,
                            (y[3] - mean2) * rstd2 * g2f.w + b2f.w);
    ((float4*)(out + (size_t)row * DIM))[t] = ov;
}

// ---------------------------------------------------------------------------
extern "C" void kernel_launch(void* const* d_in, const int* in_sizes, int n_in,
                              void* d_out, int out_size)
{
    const float* modal1 = (const float*)d_in[0];
    const float* modal2 = (const float*)d_in[1];
    const int*   um1    = (const int*)  d_in[2];
    const int*   um2    = (const int*)  d_in[3];
    const float* Wq     = (const float*)d_in[4];
    const float* bq     = (const float*)d_in[5];
    const float* Wkv    = (const float*)d_in[6];
    const float* bkv    = (const float*)d_in[7];
    const float* ln1g   = (const float*)d_in[8];
    const float* ln1b   = (const float*)d_in[9];
    // d_in[10..13] = W1,b1,W2,b2 -> FFN output is discarded by the reference.
    const float* ln2g   = (const float*)d_in[14];
    const float* ln2b   = (const float*)d_in[15];
    float* out = (float*)d_out;

    cudaFuncSetAttribute(gemm_tc,
                         cudaFuncAttributeMaxDynamicSharedMemorySize, GEMM_SMEM);
    cudaFuncSetAttribute(attn_mma,
                         cudaFuncAttributeMaxDynamicSharedMemorySize, ATT_SMEM);

    dim3 gc(BSZ * SEQ * DIM / 1024, 2);
    convert_in<<<gc, 256>>>(modal1, modal2);

    dim3 gw(16, 16, 2);
    convert_wt<<<gw, dim3(32, 8)>>>(Wq, Wkv);

    dim3 gg(DIM / 128, (BSZ * SEQ) / 128, 2);
    gemm_tc<<<gg, 256, GEMM_SMEM>>>(bq, bkv);

    dim3 ga(SEQ / QROWS, NHEAD, BSZ);
    attn_mma<<<ga, 256, ATT_SMEM>>>(um1, um2);

    epilogue_kernel<<<BSZ * SEQ, 128>>>(modal1, ln1g, ln1b, ln2g, ln2b, out);
}

// round 13
// speedup vs baseline: 1.0985x; 1.0985x over previous
#include <cuda_runtime.h>
#include <cuda_fp16.h>
#include <cstdint>
#include <math.h>

#define BSZ 4
#define SEQ 2048
#define DIM 512
#define NHEAD 8
#define HD 64
#define ATT_SCALE 0.044194173824159216f        // 1/sqrt(512)
#define EXC (ATT_SCALE * 1.4426950408889634f)  // scale * log2(e)

// ---------------------------------------------------------------------------
// Scratch (static device globals: allocation-free)
// ---------------------------------------------------------------------------
__device__ __half g_M1h[BSZ*SEQ*DIM];
__device__ __half g_M2h[BSZ*SEQ*DIM];
__device__ __half g_Wqt [DIM*DIM];   // transposed [n][k]
__device__ __half g_Wkvt[DIM*DIM];   // transposed [n][k]
__device__ __half g_Qh [BSZ*SEQ*DIM];   // pre-scaled by EXC
__device__ __half g_KVh[BSZ*SEQ*DIM];
__device__ float  g_A  [BSZ*SEQ*DIM];

// ---------------------------------------------------------------------------
// Baseline-PTX helpers (compute_80 features only: mma.sync / ldmatrix / cp.async)
// ---------------------------------------------------------------------------
__device__ __forceinline__ uint32_t smem_u32(const void* p) {
    uint32_t a;
    asm("{ .reg .u64 t; cvta.to.shared.u64 t, %1; cvt.u32.u64 %0, t; }" : "=r"(a) : "l"(p));
    return a;
}
#define SWZ(off) ((off) ^ (((off) >> 3) & 0x70))

#define LDSM_X4(r0,r1,r2,r3,a) \
    asm volatile("ldmatrix.sync.aligned.m8n8.x4.shared.b16 {%0,%1,%2,%3}, [%4];" \
        : "=r"(r0),"=r"(r1),"=r"(r2),"=r"(r3) : "r"(a))
#define LDSM_X4T(r0,r1,r2,r3,a) \
    asm volatile("ldmatrix.sync.aligned.m8n8.x4.trans.shared.b16 {%0,%1,%2,%3}, [%4];" \
        : "=r"(r0),"=r"(r1),"=r"(r2),"=r"(r3) : "r"(a))

__device__ __forceinline__ void mma_f16(float c[4], uint32_t a0, uint32_t a1,
                                        uint32_t a2, uint32_t a3,
                                        uint32_t b0, uint32_t b1) {
    asm volatile(
        "mma.sync.aligned.m16n8k16.row.col.f32.f16.f16.f32 "
        "{%0,%1,%2,%3}, {%4,%5,%6,%7}, {%8,%9}, {%0,%1,%2,%3};"
        : "+f"(c[0]), "+f"(c[1]), "+f"(c[2]), "+f"(c[3])
        : "r"(a0), "r"(a1), "r"(a2), "r"(a3), "r"(b0), "r"(b1));
}

#define CP_ASYNC16(dst, src) \
    asm volatile("cp.async.cg.shared.global [%0], [%1], 16;" :: "r"(dst), "l"(src))
#define CP_COMMIT() asm volatile("cp.async.commit_group;" ::: "memory")
#define CP_WAIT1()  asm volatile("cp.async.wait_group 1;" ::: "memory")
#define CP_WAIT0()  asm volatile("cp.async.wait_group 0;" ::: "memory")

__device__ __forceinline__ uint32_t cvt_h2(float hi, float lo) {
    uint32_t r;
    asm("cvt.rn.f16x2.f32 %0, %1, %2;" : "=r"(r) : "f"(hi), "f"(lo));
    return r;
}
#define EX2_H2(d, a) asm("ex2.approx.f16x2 %0, %1;" : "=r"(d) : "r"(a))

// ldmatrix address builders (row stride 128B, SW128 swizzle) — prologue only
__device__ __forceinline__ uint32_t lm_a(uint32_t base, int lane, int m0, int k0) {
    int mat = lane >> 3, r = lane & 7;
    int row = m0 + r + ((mat & 1) ? 8 : 0);
    int colb = (k0 + ((mat & 2) ? 8 : 0)) * 2;
    uint32_t off = (uint32_t)row * 128u + (uint32_t)colb;
    return base + SWZ(off);
}
__device__ __forceinline__ uint32_t lm_bs(uint32_t base, int lane, int n0, int k0) {
    int mat = lane >> 3, r = lane & 7;
    int row = n0 + r + ((mat & 2) ? 8 : 0);
    int colb = (k0 + ((mat & 1) ? 8 : 0)) * 2;
    uint32_t off = (uint32_t)row * 128u + (uint32_t)colb;
    return base + SWZ(off);
}

// ---------------------------------------------------------------------------
// Convert modal inputs fp32 -> fp16 (elementwise).
// ---------------------------------------------------------------------------
__global__ __launch_bounds__(256) void convert_in(
    const float* __restrict__ m1, const float* __restrict__ m2)
{
    const float* src = blockIdx.y ? m2 : m1;
    __half* dst = blockIdx.y ? g_M2h : g_M1h;
    size_t i4 = ((size_t)blockIdx.x * 256 + threadIdx.x) * 4;
    float4 v = *(const float4*)(src + i4);
    uint2 w = make_uint2(cvt_h2(v.y, v.x), cvt_h2(v.w, v.z));
    *(uint2*)(dst + i4) = w;
}

// ---------------------------------------------------------------------------
// Convert + transpose W (512x512): Wt[n][k] = W[k][n], fp16 out.
// ---------------------------------------------------------------------------
__global__ __launch_bounds__(256) void convert_wt(
    const float* __restrict__ Wq, const float* __restrict__ Wkv)
{
    __shared__ float t[32][33];
    const float* W = blockIdx.z ? Wkv : Wq;
    __half* Wt = blockIdx.z ? g_Wkvt : g_Wqt;
    int k0 = blockIdx.x * 32, n0 = blockIdx.y * 32;
    int tx = threadIdx.x, ty = threadIdx.y;
    #pragma unroll
    for (int i = 0; i < 4; i++)
        t[ty + 8 * i][tx] = W[(size_t)(k0 + ty + 8 * i) * DIM + n0 + tx];
    __syncthreads();
    #pragma unroll
    for (int i = 0; i < 4; i++)
        Wt[(size_t)(n0 + ty + 8 * i) * DIM + k0 + tx] =
            __float2half(t[tx][ty + 8 * i]);
}

// ---------------------------------------------------------------------------
// Tensor-core projection GEMM: C(8192x512) = A @ W + bias, fp16 in/out.
// Q output (blockIdx.z==0) is PRE-SCALED by EXC for the attention softmax.
// ---------------------------------------------------------------------------
#define GSM_A0 0
#define GSM_B0 16384
#define GSM_A1 32768
#define GSM_B1 49152
#define GEMM_SMEM 65536

__global__ __launch_bounds__(256) void gemm_tc(
    const float* __restrict__ bq, const float* __restrict__ bkv)
{
    extern __shared__ char smem[];
    const uint32_t sb = smem_u32(smem);

    const __half* A; const __half* Wt;
    const float* bias; __half* C;
    if (blockIdx.z == 0) { A = g_M1h; Wt = g_Wqt;  bias = bq;  C = g_Qh;  }
    else                 { A = g_M2h; Wt = g_Wkvt; bias = bkv; C = g_KVh; }
    const float escale = (blockIdx.z == 0) ? EXC : 1.0f;

    const int tid = threadIdx.x;
    const int lane = tid & 31, wid = tid >> 5;
    const int g = lane >> 2, tig = lane & 3;
    const int wm = wid & 1, wn = wid >> 1;
    const int m0 = blockIdx.y * 128, n0 = blockIdx.x * 128;

    const int lrow = tid >> 3, lch = tid & 7;

    {
        const __half* As = A  + (size_t)(m0 + lrow) * DIM + lch * 8;
        const __half* Bs = Wt + (size_t)(n0 + lrow) * DIM + lch * 8;
        #pragma unroll
        for (int p = 0; p < 4; p++) {
            uint32_t off = SWZ((uint32_t)(lrow + p * 32) * 128u + (uint32_t)lch * 16u);
            CP_ASYNC16(sb + GSM_A0 + off, As + (size_t)p * 32 * DIM);
            CP_ASYNC16(sb + GSM_B0 + off, Bs + (size_t)p * 32 * DIM);
        }
        CP_COMMIT();
    }

    float acc[4][4][4];
    #pragma unroll
    for (int m = 0; m < 4; m++)
        #pragma unroll
        for (int n = 0; n < 4; n++)
            #pragma unroll
            for (int k = 0; k < 4; k++) acc[m][n][k] = 0.f;

    for (int kt = 0; kt < 8; kt++) {
        const int cur = kt & 1, nxt = cur ^ 1;
        if (kt < 7) {
            const __half* As = A  + (size_t)(m0 + lrow) * DIM + (kt + 1) * 64 + lch * 8;
            const __half* Bs = Wt + (size_t)(n0 + lrow) * DIM + (kt + 1) * 64 + lch * 8;
            const uint32_t ab = sb + (nxt ? GSM_A1 : GSM_A0);
            const uint32_t bb = sb + (nxt ? GSM_B1 : GSM_B0);
            #pragma unroll
            for (int p = 0; p < 4; p++) {
                uint32_t off = SWZ((uint32_t)(lrow + p * 32) * 128u + (uint32_t)lch * 16u);
                CP_ASYNC16(ab + off, As + (size_t)p * 32 * DIM);
                CP_ASYNC16(bb + off, Bs + (size_t)p * 32 * DIM);
            }
            CP_COMMIT();
            CP_WAIT1();
        } else {
            CP_WAIT0();
        }
        __syncthreads();

        const uint32_t abase = sb + (cur ? GSM_A1 : GSM_A0);
        const uint32_t bbase = sb + (cur ? GSM_B1 : GSM_B0);

        #pragma unroll
        for (int kf = 0; kf < 4; kf++) {
            uint32_t qa[4][4];
            #pragma unroll
            for (int m = 0; m < 4; m++)
                LDSM_X4(qa[m][0], qa[m][1], qa[m][2], qa[m][3],
                        lm_a(abase, lane, wm * 64 + m * 16, kf * 16));
            uint32_t bb[2][4];
            #pragma unroll
            for (int np = 0; np < 2; np++)
                LDSM_X4(bb[np][0], bb[np][1], bb[np][2], bb[np][3],
                        lm_bs(bbase, lane, wn * 32 + np * 16, kf * 16));
            #pragma unroll
            for (int m = 0; m < 4; m++)
                #pragma unroll
                for (int np = 0; np < 2; np++)
                    #pragma unroll
                    for (int nt = 0; nt < 2; nt++)
                        mma_f16(acc[m][np * 2 + nt],
                                qa[m][0], qa[m][1], qa[m][2], qa[m][3],
                                bb[np][nt * 2], bb[np][nt * 2 + 1]);
        }
        __syncthreads();
    }

    float2 bf[4];
    #pragma unroll
    for (int n = 0; n < 4; n++)
        bf[n] = *(const float2*)&bias[n0 + wn * 32 + n * 8 + 2 * tig];

    #pragma unroll
    for (int m = 0; m < 4; m++) {
        int row = m0 + wm * 64 + m * 16 + g;
        #pragma unroll
        for (int n = 0; n < 4; n++) {
            int col = n0 + wn * 32 + n * 8 + 2 * tig;
            *(uint32_t*)(C + (size_t)row * DIM + col) =
                cvt_h2((acc[m][n][1] + bf[n].y) * escale,
                       (acc[m][n][0] + bf[n].x) * escale);
            *(uint32_t*)(C + (size_t)(row + 8) * DIM + col) =
                cvt_h2((acc[m][n][3] + bf[n].y) * escale,
                       (acc[m][n][2] + bf[n].x) * escale);
        }
    }
}

// ---------------------------------------------------------------------------
// fp16 mma.sync flash attention.
// 128 threads / 4 warps, CTA = 128 q-rows, 32 q-rows (2 m-tiles) per warp.
// Smem traffic per q-row halved (K frags feed 2 m-tiles) AND 2 CTAs/SM so
// barrier bubbles in one CTA are covered by the other (R12 failed on this).
// Q pre-scaled by EXC; ex2.f16x2 softmax; row sums via all-ones tensor column.
// ---------------------------------------------------------------------------
#define QROWS 128
#define SMQ   0
#define SMK0  16384
#define SMM2  49152
#define ATT_SMEM (49152 + 2 * 128 * 4)
#define ONES_H2 0x3C003C00u

__global__ __launch_bounds__(128, 2) void attn_mma(
    const int* __restrict__ um1, const int* __restrict__ um2)
{
    extern __shared__ char smem[];
    const uint32_t sb = smem_u32(smem);
    float* m2f = (float*)(smem + SMM2);

    const int tid = threadIdx.x;
    const int lane = tid & 31, wid = tid >> 5;
    const int g = lane >> 2, tig = lane & 3;
    const int b = blockIdx.z, h = blockIdx.y, qt = blockIdx.x;
    const int mbase = wid * 32;

    // --- prologue: async K tile 0, additive m2 tile 0, plain Q tile ---
    {
        const __half* src = g_KVh + (size_t)(b * SEQ) * DIM + h * HD;
        #pragma unroll
        for (int p = 0; p < 8; p++) {
            int row = (tid >> 3) + p * 16, ch = tid & 7;
            uint32_t dst = sb + SMK0 + SWZ((uint32_t)row * 128u + (uint32_t)ch * 16u);
            CP_ASYNC16(dst, src + (size_t)row * DIM + ch * 8);
        }
        CP_COMMIT();
        m2f[tid] = (um2[b * SEQ + tid] != 0) ? 0.0f : -1e30f;

        const __half* qs = g_Qh + (size_t)(b * SEQ + qt * QROWS) * DIM + h * HD;
        #pragma unroll
        for (int p = 0; p < 8; p++) {
            int row = (tid >> 3) + p * 16, ch = tid & 7;
            uint4 v = *(const uint4*)(qs + (size_t)row * DIM + ch * 8);
            *(uint4*)(smem + SMQ + SWZ((uint32_t)row * 128u + (uint32_t)ch * 16u)) = v;
        }
    }

    bool rv[2][2];
    #pragma unroll
    for (int m = 0; m < 2; m++)
        #pragma unroll
        for (int r = 0; r < 2; r++)
            rv[m][r] = um1[b * SEQ + qt * QROWS + mbase + m * 16 + r * 8 + g] != 0;

    // --- precomputed LDSM lane bases (SWZ is affine for 8-multiple rows) ---
    const int matq = lane >> 3, rl = lane & 7;
    const uint32_t rsw = (uint32_t)rl << 4;
    const uint32_t row_bs = (uint32_t)(rl + ((matq & 2) ? 8 : 0)) * 128u;
    const uint32_t cl_bs  = (matq & 1) ? 16u : 0u;
    uint32_t bsk[4];
    #pragma unroll
    for (int kf = 0; kf < 4; kf++)
        bsk[kf] = sb + SMK0 + row_bs + (((uint32_t)kf * 32u + cl_bs) ^ rsw);
    const uint32_t row_bo = (uint32_t)(rl + ((matq & 1) ? 8 : 0)) * 128u;
    const uint32_t cl_bo  = (matq & 2) ? 16u : 0u;
    uint32_t bok[4];
    #pragma unroll
    for (int dp = 0; dp < 4; dp++)
        bok[dp] = sb + SMK0 + row_bo + (((uint32_t)dp * 32u + cl_bo) ^ rsw);

    __syncthreads();   // Q visible

    // Q a-frags (persistent): 2 m-tiles per warp
    uint32_t qa[2][4][4];
    #pragma unroll
    for (int m = 0; m < 2; m++)
        #pragma unroll
        for (int kf = 0; kf < 4; kf++)
            LDSM_X4(qa[m][kf][0], qa[m][kf][1], qa[m][kf][2], qa[m][kf][3],
                    lm_a(sb + SMQ, lane, mbase + m * 16, kf * 16));

    float oc[2][8][4];
    #pragma unroll
    for (int m = 0; m < 2; m++)
        #pragma unroll
        for (int n = 0; n < 8; n++)
            #pragma unroll
            for (int k = 0; k < 4; k++) oc[m][n][k] = 0.f;
    float os[2][4];
    #pragma unroll
    for (int m = 0; m < 2; m++)
        #pragma unroll
        for (int k = 0; k < 4; k++) os[m][k] = 0.f;

    for (int kt = 0; kt < 16; kt++) {
        const int cur = kt & 1, nxt = cur ^ 1;
        if (kt < 15) {
            const __half* src =
                g_KVh + (size_t)(b * SEQ + (kt + 1) * 128) * DIM + h * HD;
            #pragma unroll
            for (int p = 0; p < 8; p++) {
                int row = (tid >> 3) + p * 16, ch = tid & 7;
                uint32_t dst = sb + SMK0 + (uint32_t)nxt * 16384u +
                               SWZ((uint32_t)row * 128u + (uint32_t)ch * 16u);
                CP_ASYNC16(dst, src + (size_t)row * DIM + ch * 8);
            }
            CP_COMMIT();
            m2f[nxt * 128 + tid] = (um2[b * SEQ + (kt + 1) * 128 + tid] != 0) ? 0.0f : -1e30f;
            CP_WAIT1();
        } else {
            CP_WAIT0();
        }
        __syncthreads();   // K[cur] + m2[cur] ready

        const uint32_t koff = (uint32_t)cur * 16384u;
        uint32_t bsc[4], boc[4];
        #pragma unroll
        for (int i = 0; i < 4; i++) { bsc[i] = bsk[i] + koff; boc[i] = bok[i] + koff; }
        const float* m2c = m2f + cur * 128 + 2 * tig;

        #pragma unroll
        for (int c4 = 0; c4 < 4; c4++) {
            // ---- S chunk: 32 keys x 2 m-tiles ----
            float sc[2][4][4];
            #pragma unroll
            for (int m = 0; m < 2; m++)
                #pragma unroll
                for (int n = 0; n < 4; n++)
                    #pragma unroll
                    for (int k = 0; k < 4; k++) sc[m][n][k] = 0.f;

            #pragma unroll
            for (int np = 0; np < 2; np++) {
                const uint32_t roff = (uint32_t)(c4 * 32 + np * 16) * 128u;
                uint32_t bb[4][4];
                #pragma unroll
                for (int kf = 0; kf < 4; kf++)
                    LDSM_X4(bb[kf][0], bb[kf][1], bb[kf][2], bb[kf][3],
                            bsc[kf] + roff);
                #pragma unroll
                for (int m = 0; m < 2; m++)
                    #pragma unroll
                    for (int nt = 0; nt < 2; nt++)
                        #pragma unroll
                        for (int kf = 0; kf < 4; kf++)
                            mma_f16(sc[m][np * 2 + nt],
                                    qa[m][kf][0], qa[m][kf][1], qa[m][kf][2], qa[m][kf][3],
                                    bb[kf][nt * 2], bb[kf][nt * 2 + 1]);
            }

            // ---- softmax: masked add -> f16x2 pack -> ex2.f16x2 ----
            uint32_t aP[2][2][4];
            #pragma unroll
            for (int m = 0; m < 2; m++) {
                #pragma unroll
                for (int n = 0; n < 4; n++) {
                    float2 mv = *(const float2*)&m2c[c4 * 32 + n * 8];
                    float x0 = sc[m][n][0] + mv.x;
                    float x1 = sc[m][n][1] + mv.y;
                    float x2 = sc[m][n][2] + mv.x;
                    float x3 = sc[m][n][3] + mv.y;
                    x0 = rv[m][0] ? x0 : 0.0f;   // exp2(0)=1 -> uniform row
                    x1 = rv[m][0] ? x1 : 0.0f;
                    x2 = rv[m][1] ? x2 : 0.0f;
                    x3 = rv[m][1] ? x3 : 0.0f;
                    uint32_t plo = cvt_h2(x1, x0);
                    uint32_t phi = cvt_h2(x3, x2);
                    EX2_H2(plo, plo);
                    EX2_H2(phi, phi);
                    aP[m][n >> 1][(n & 1) * 2 + 0] = plo;
                    aP[m][n >> 1][(n & 1) * 2 + 1] = phi;
                }
            }

            // ---- O += P @ K (V = K); B-frags loaded ONCE, feed both m-tiles ----
            #pragma unroll
            for (int kf = 0; kf < 2; kf++) {
                const uint32_t roff = (uint32_t)(c4 * 32 + kf * 16) * 128u;
                #pragma unroll
                for (int m = 0; m < 2; m++)
                    mma_f16(os[m], aP[m][kf][0], aP[m][kf][1],
                            aP[m][kf][2], aP[m][kf][3], ONES_H2, ONES_H2);
                #pragma unroll
                for (int dp = 0; dp < 4; dp++) {
                    uint32_t r0, r1, r2, r3;
                    LDSM_X4T(r0, r1, r2, r3, boc[dp] + roff);
                    #pragma unroll
                    for (int m = 0; m < 2; m++) {
                        mma_f16(oc[m][dp * 2],
                                aP[m][kf][0], aP[m][kf][1], aP[m][kf][2], aP[m][kf][3],
                                r0, r1);
                        mma_f16(oc[m][dp * 2 + 1],
                                aP[m][kf][0], aP[m][kf][1], aP[m][kf][2], aP[m][kf][3],
                                r2, r3);
                    }
                }
            }
        }
        __syncthreads();   // done reading K[cur] before overwrite
    }

    // ---- finalize: row sums in os[m][0] (row g) and os[m][2] (row g+8) ----
    float* Og = g_A + (size_t)(b * SEQ + qt * QROWS) * DIM + h * HD;
    #pragma unroll
    for (int m = 0; m < 2; m++) {
        const float inv0 = 1.0f / os[m][0];
        const float inv1 = 1.0f / os[m][2];
        int row0 = mbase + m * 16 + g;
        #pragma unroll
        for (int dt = 0; dt < 8; dt++) {
            int col = dt * 8 + 2 * tig;
            *(float2*)(Og + (size_t)row0 * DIM + col) =
                make_float2(oc[m][dt][0] * inv0, oc[m][dt][1] * inv0);
            *(float2*)(Og + (size_t)(row0 + 8) * DIM + col) =
                make_float2(oc[m][dt][2] * inv1, oc[m][dt][3] * inv1);
        }
    }
}

// ---------------------------------------------------------------------------
// Epilogue: x = LN1(attn + modal1); out = LN2(attn + x).  (FFN is dead code.)
// ---------------------------------------------------------------------------
__global__ __launch_bounds__(128) void epilogue_kernel(
    const float* __restrict__ modal1,
    const float* __restrict__ g1, const float* __restrict__ b1,
    const float* __restrict__ g2, const float* __restrict__ b2,
    float* __restrict__ out)
{
    __shared__ float red[2][4];
    const int row = blockIdx.x;
    const int t = threadIdx.x;
    const int lane = t & 31, wid = t >> 5;

    const float4 av = ((const float4*)(g_A    + (size_t)row * DIM))[t];
    const float4 mv = ((const float4*)(modal1 + (size_t)row * DIM))[t];
    float x[4] = {av.x + mv.x, av.y + mv.y, av.z + mv.z, av.w + mv.w};

    float s = x[0] + x[1] + x[2] + x[3];
    float q = x[0]*x[0] + x[1]*x[1] + x[2]*x[2] + x[3]*x[3];
    #pragma unroll
    for (int off = 16; off > 0; off >>= 1) {
        s += __shfl_xor_sync(0xffffffffu, s, off);
        q += __shfl_xor_sync(0xffffffffu, q, off);
    }
    if (lane == 0) { red[0][wid] = s; red[1][wid] = q; }
    __syncthreads();
    s = red[0][0] + red[0][1] + red[0][2] + red[0][3];
    q = red[1][0] + red[1][1] + red[1][2] + red[1][3];
    float mean = s * (1.0f / 512.0f);
    float var  = q * (1.0f / 512.0f) - mean * mean;
    float rstd = rsqrtf(var + 1e-5f);

    const float4 g1f = ((const float4*)g1)[t];
    const float4 b1f = ((const float4*)b1)[t];
    float y[4];
    y[0] = av.x + ((x[0] - mean) * rstd * g1f.x + b1f.x);
    y[1] = av.y + ((x[1] - mean) * rstd * g1f.y + b1f.y);
    y[2] = av.z + ((x[2] - mean) * rstd * g1f.z + b1f.z);
    y[3] = av.w + ((x[3] - mean) * rstd * g1f.w + b1f.w);

    __syncthreads();
    s = y[0] + y[1] + y[2] + y[3];
    q = y[0]*y[0] + y[1]*y[1] + y[2]*y[2] + y[3]*y[3];
    #pragma unroll
    for (int off = 16; off > 0; off >>= 1) {
        s += __shfl_xor_sync(0xffffffffu, s, off);
        q += __shfl_xor_sync(0xffffffffu, q, off);
    }
    if (lane == 0) { red[0][wid] = s; red[1][wid] = q; }
    __syncthreads();
    s = red[0][0] + red[0][1] + red[0][2] + red[0][3];
    q = red[1][0] + red[1][1] + red[1][2] + red[1][3];
    float mean2 = s * (1.0f / 512.0f);
    float var2  = q * (1.0f / 512.0f) - mean2 * mean2;
    float rstd2 = rsqrtf(var2 + 1e-5f);

    const float4 g2f = ((const float4*)g2)[t];
    const float4 b2f = ((const float4*)b2)[t];
    float4 ov = make_float4((y[0] - mean2) * rstd2 * g2f.x + b2f.x,
                            (y[1] - mean2) * rstd2 * g2f.y + b2f.y,
                            (y[2] - mean2) * rstd2 * g2f.z + b2f.z,
                            (y[3] - mean2) * rstd2 * g2f.w + b2f.w);
    ((float4*)(out + (size_t)row * DIM))[t] = ov;
}

// ---------------------------------------------------------------------------
extern "C" void kernel_launch(void* const* d_in, const int* in_sizes, int n_in,
                              void* d_out, int out_size)
{
    const float* modal1 = (const float*)d_in[0];
    const float* modal2 = (const float*)d_in[1];
    const int*   um1    = (const int*)  d_in[2];
    const int*   um2    = (const int*)  d_in[3];
    const float* Wq     = (const float*)d_in[4];
    const float* bq     = (const float*)d_in[5];
    const float* Wkv    = (const float*)d_in[6];
    const float* bkv    = (const float*)d_in[7];
    const float* ln1g   = (const float*)d_in[8];
    const float* ln1b   = (const float*)d_in[9];
    // d_in[10..13] = W1,b1,W2,b2 -> FFN output is discarded by the reference.
    const float* ln2g   = (const float*)d_in[14];
    const float* ln2b   = (const float*)d_in[15];
    float* out = (float*)d_out;

    cudaFuncSetAttribute(gemm_tc,
                         cudaFuncAttributeMaxDynamicSharedMemorySize, GEMM_SMEM);
    cudaFuncSetAttribute(attn_mma,
                         cudaFuncAttributeMaxDynamicSharedMemorySize, ATT_SMEM);

    dim3 gc(BSZ * SEQ * DIM / 1024, 2);
    convert_in<<<gc, 256>>>(modal1, modal2);

    dim3 gw(16, 16, 2);
    convert_wt<<<gw, dim3(32, 8)>>>(Wq, Wkv);

    dim3 gg(DIM / 128, (BSZ * SEQ) / 128, 2);
    gemm_tc<<<gg, 256, GEMM_SMEM>>>(bq, bkv);

    dim3 ga(SEQ / QROWS, NHEAD, BSZ);
    attn_mma<<<ga, 128, ATT_SMEM>>>(um1, um2);

    epilogue_kernel<<<BSZ * SEQ, 128>>>(modal1, ln1g, ln1b, ln2g, ln2b, out);
}

// round 14
// speedup vs baseline: 1.1139x; 1.0141x over previous
#include <cuda_runtime.h>
#include <cuda_fp16.h>
#include <cstdint>
#include <math.h>

#define BSZ 4
#define SEQ 2048
#define DIM 512
#define NHEAD 8
#define HD 64
#define ATT_SCALE 0.044194173824159216f        // 1/sqrt(512)
#define EXC (ATT_SCALE * 1.4426950408889634f)  // scale * log2(e)

// ---------------------------------------------------------------------------
// Scratch (static device globals: allocation-free)
// ---------------------------------------------------------------------------
__device__ __half g_Wqt [DIM*DIM];   // transposed [n][k]
__device__ __half g_Wkvt[DIM*DIM];   // transposed [n][k]
__device__ __half g_Qh [BSZ*SEQ*DIM];   // pre-scaled by EXC
__device__ __half g_KVh[BSZ*SEQ*DIM];
__device__ float  g_A  [BSZ*SEQ*DIM];

// ---------------------------------------------------------------------------
// Baseline-PTX helpers (compute_80 features only: mma.sync / ldmatrix / cp.async)
// ---------------------------------------------------------------------------
__device__ __forceinline__ uint32_t smem_u32(const void* p) {
    uint32_t a;
    asm("{ .reg .u64 t; cvta.to.shared.u64 t, %1; cvt.u32.u64 %0, t; }" : "=r"(a) : "l"(p));
    return a;
}
#define SWZ(off) ((off) ^ (((off) >> 3) & 0x70))

#define LDSM_X4(r0,r1,r2,r3,a) \
    asm volatile("ldmatrix.sync.aligned.m8n8.x4.shared.b16 {%0,%1,%2,%3}, [%4];" \
        : "=r"(r0),"=r"(r1),"=r"(r2),"=r"(r3) : "r"(a))
#define LDSM_X4T(r0,r1,r2,r3,a) \
    asm volatile("ldmatrix.sync.aligned.m8n8.x4.trans.shared.b16 {%0,%1,%2,%3}, [%4];" \
        : "=r"(r0),"=r"(r1),"=r"(r2),"=r"(r3) : "r"(a))

__device__ __forceinline__ void mma_f16(float c[4], uint32_t a0, uint32_t a1,
                                        uint32_t a2, uint32_t a3,
                                        uint32_t b0, uint32_t b1) {
    asm volatile(
        "mma.sync.aligned.m16n8k16.row.col.f32.f16.f16.f32 "
        "{%0,%1,%2,%3}, {%4,%5,%6,%7}, {%8,%9}, {%0,%1,%2,%3};"
        : "+f"(c[0]), "+f"(c[1]), "+f"(c[2]), "+f"(c[3])
        : "r"(a0), "r"(a1), "r"(a2), "r"(a3), "r"(b0), "r"(b1));
}

#define CP_ASYNC16(dst, src) \
    asm volatile("cp.async.cg.shared.global [%0], [%1], 16;" :: "r"(dst), "l"(src))
#define CP_COMMIT() asm volatile("cp.async.commit_group;" ::: "memory")
#define CP_WAIT1()  asm volatile("cp.async.wait_group 1;" ::: "memory")
#define CP_WAIT0()  asm volatile("cp.async.wait_group 0;" ::: "memory")

__device__ __forceinline__ uint32_t cvt_h2(float hi, float lo) {
    uint32_t r;
    asm("cvt.rn.f16x2.f32 %0, %1, %2;" : "=r"(r) : "f"(hi), "f"(lo));
    return r;
}
#define EX2_H2(d, a) asm("ex2.approx.f16x2 %0, %1;" : "=r"(d) : "r"(a))

// ldmatrix address builders (row stride 128B, SW128 swizzle) — prologue only
__device__ __forceinline__ uint32_t lm_a(uint32_t base, int lane, int m0, int k0) {
    int mat = lane >> 3, r = lane & 7;
    int row = m0 + r + ((mat & 1) ? 8 : 0);
    int colb = (k0 + ((mat & 2) ? 8 : 0)) * 2;
    uint32_t off = (uint32_t)row * 128u + (uint32_t)colb;
    return base + SWZ(off);
}
__device__ __forceinline__ uint32_t lm_bs(uint32_t base, int lane, int n0, int k0) {
    int mat = lane >> 3, r = lane & 7;
    int row = n0 + r + ((mat & 2) ? 8 : 0);
    int colb = (k0 + ((mat & 1) ? 8 : 0)) * 2;
    uint32_t off = (uint32_t)row * 128u + (uint32_t)colb;
    return base + SWZ(off);
}

// ---------------------------------------------------------------------------
// Convert + transpose W (512x512): Wt[n][k] = W[k][n], fp16 out.
// ---------------------------------------------------------------------------
__global__ __launch_bounds__(256) void convert_wt(
    const float* __restrict__ Wq, const float* __restrict__ Wkv)
{
    __shared__ float t[32][33];
    const float* W = blockIdx.z ? Wkv : Wq;
    __half* Wt = blockIdx.z ? g_Wkvt : g_Wqt;
    int k0 = blockIdx.x * 32, n0 = blockIdx.y * 32;
    int tx = threadIdx.x, ty = threadIdx.y;
    #pragma unroll
    for (int i = 0; i < 4; i++)
        t[ty + 8 * i][tx] = W[(size_t)(k0 + ty + 8 * i) * DIM + n0 + tx];
    __syncthreads();
    #pragma unroll
    for (int i = 0; i < 4; i++)
        Wt[(size_t)(n0 + ty + 8 * i) * DIM + k0 + tx] =
            __float2half(t[tx][ty + 8 * i]);
}

// ---------------------------------------------------------------------------
// Tensor-core projection GEMM: C(8192x512) = A(fp32!) @ W + bias, fp16 out.
// A is loaded fp32 from the ORIGINAL inputs (LDG.128 -> cvt -> STS, register
// double-buffered), fusing the fp32->fp16 conversion into the GEMM and
// deleting the separate convert pass. B (fp16 Wt) stays on cp.async.
// Q output (blockIdx.z==0) is PRE-SCALED by EXC for the attention softmax.
// ---------------------------------------------------------------------------
#define GSM_A0 0
#define GSM_B0 16384
#define GSM_A1 32768
#define GSM_B1 49152
#define GEMM_SMEM 65536

__global__ __launch_bounds__(256) void gemm_tc(
    const float* __restrict__ M1, const float* __restrict__ M2,
    const float* __restrict__ bq, const float* __restrict__ bkv)
{
    extern __shared__ char smem[];
    const uint32_t sb = smem_u32(smem);

    const float* A32; const __half* Wt;
    const float* bias; __half* C;
    if (blockIdx.z == 0) { A32 = M1; Wt = g_Wqt;  bias = bq;  C = g_Qh;  }
    else                 { A32 = M2; Wt = g_Wkvt; bias = bkv; C = g_KVh; }
    const float escale = (blockIdx.z == 0) ? EXC : 1.0f;

    const int tid = threadIdx.x;
    const int lane = tid & 31, wid = tid >> 5;
    const int g = lane >> 2, tig = lane & 3;
    const int wm = wid & 1, wn = wid >> 1;
    const int m0 = blockIdx.y * 128, n0 = blockIdx.x * 128;

    const int lrow = tid >> 3, lch = tid & 7;   // 32 rows x 8 k-chunks of 8

    // A gmem base for this thread's 4 (row, chunk) positions
    const float* Ab = A32 + (size_t)(m0 + lrow) * DIM + lch * 8;
    // smem offsets for the 4 positions (constant across k-tiles)
    uint32_t asw[4];
    #pragma unroll
    for (int p = 0; p < 4; p++)
        asw[p] = SWZ((uint32_t)(lrow + p * 32) * 128u + (uint32_t)lch * 16u);

    float4 pre[4][2];

    // ---- prologue: k-tile 0 ----
    {
        const __half* Bs = Wt + (size_t)(n0 + lrow) * DIM + lch * 8;
        #pragma unroll
        for (int p = 0; p < 4; p++)
            CP_ASYNC16(sb + GSM_B0 + asw[p], Bs + (size_t)p * 32 * DIM);
        CP_COMMIT();
        #pragma unroll
        for (int p = 0; p < 4; p++) {
            pre[p][0] = *(const float4*)(Ab + (size_t)p * 32 * DIM);
            pre[p][1] = *(const float4*)(Ab + (size_t)p * 32 * DIM + 4);
        }
        #pragma unroll
        for (int p = 0; p < 4; p++) {
            uint4 w = make_uint4(cvt_h2(pre[p][0].y, pre[p][0].x),
                                 cvt_h2(pre[p][0].w, pre[p][0].z),
                                 cvt_h2(pre[p][1].y, pre[p][1].x),
                                 cvt_h2(pre[p][1].w, pre[p][1].z));
            *(uint4*)(smem + GSM_A0 + asw[p]) = w;
        }
        CP_WAIT0();
    }
    __syncthreads();

    float acc[4][4][4];
    #pragma unroll
    for (int m = 0; m < 4; m++)
        #pragma unroll
        for (int n = 0; n < 4; n++)
            #pragma unroll
            for (int k = 0; k < 4; k++) acc[m][n][k] = 0.f;

    for (int kt = 0; kt < 8; kt++) {
        const int cur = kt & 1, nxt = cur ^ 1;
        if (kt < 7) {
            // issue next A LDGs (fp32) + next B cp.async; both complete under mma
            const float* An = Ab + (kt + 1) * 64;
            #pragma unroll
            for (int p = 0; p < 4; p++) {
                pre[p][0] = *(const float4*)(An + (size_t)p * 32 * DIM);
                pre[p][1] = *(const float4*)(An + (size_t)p * 32 * DIM + 4);
            }
            const __half* Bs = Wt + (size_t)(n0 + lrow) * DIM + (kt + 1) * 64 + lch * 8;
            const uint32_t bb = sb + (nxt ? GSM_B1 : GSM_B0);
            #pragma unroll
            for (int p = 0; p < 4; p++)
                CP_ASYNC16(bb + asw[p], Bs + (size_t)p * 32 * DIM);
            CP_COMMIT();
        }

        const uint32_t abase = sb + (cur ? GSM_A1 : GSM_A0);
        const uint32_t bbase = sb + (cur ? GSM_B1 : GSM_B0);

        #pragma unroll
        for (int kf = 0; kf < 4; kf++) {
            uint32_t qa[4][4];
            #pragma unroll
            for (int m = 0; m < 4; m++)
                LDSM_X4(qa[m][0], qa[m][1], qa[m][2], qa[m][3],
                        lm_a(abase, lane, wm * 64 + m * 16, kf * 16));
            uint32_t bb[2][4];
            #pragma unroll
            for (int np = 0; np < 2; np++)
                LDSM_X4(bb[np][0], bb[np][1], bb[np][2], bb[np][3],
                        lm_bs(bbase, lane, wn * 32 + np * 16, kf * 16));
            #pragma unroll
            for (int m = 0; m < 4; m++)
                #pragma unroll
                for (int np = 0; np < 2; np++)
                    #pragma unroll
                    for (int nt = 0; nt < 2; nt++)
                        mma_f16(acc[m][np * 2 + nt],
                                qa[m][0], qa[m][1], qa[m][2], qa[m][3],
                                bb[np][nt * 2], bb[np][nt * 2 + 1]);
        }

        if (kt < 7) {
            // convert + store next A tile; wait next B
            const uint32_t ab = sb + (nxt ? GSM_A1 : GSM_A0);
            #pragma unroll
            for (int p = 0; p < 4; p++) {
                uint4 w = make_uint4(cvt_h2(pre[p][0].y, pre[p][0].x),
                                     cvt_h2(pre[p][0].w, pre[p][0].z),
                                     cvt_h2(pre[p][1].y, pre[p][1].x),
                                     cvt_h2(pre[p][1].w, pre[p][1].z));
                *(uint4*)(smem + (ab - sb) + asw[p]) = w;
            }
            CP_WAIT0();
        }
        __syncthreads();
    }

    float2 bf[4];
    #pragma unroll
    for (int n = 0; n < 4; n++)
        bf[n] = *(const float2*)&bias[n0 + wn * 32 + n * 8 + 2 * tig];

    #pragma unroll
    for (int m = 0; m < 4; m++) {
        int row = m0 + wm * 64 + m * 16 + g;
        #pragma unroll
        for (int n = 0; n < 4; n++) {
            int col = n0 + wn * 32 + n * 8 + 2 * tig;
            *(uint32_t*)(C + (size_t)row * DIM + col) =
                cvt_h2((acc[m][n][1] + bf[n].y) * escale,
                       (acc[m][n][0] + bf[n].x) * escale);
            *(uint32_t*)(C + (size_t)(row + 8) * DIM + col) =
                cvt_h2((acc[m][n][3] + bf[n].y) * escale,
                       (acc[m][n][2] + bf[n].x) * escale);
        }
    }
}

// ---------------------------------------------------------------------------
// fp16 mma.sync flash attention.  [R13 structure — unchanged]
// 128 threads / 4 warps, CTA = 128 q-rows, 32 q-rows (2 m-tiles) per warp.
// ---------------------------------------------------------------------------
#define QROWS 128
#define SMQ   0
#define SMK0  16384
#define SMM2  49152
#define ATT_SMEM (49152 + 2 * 128 * 4)
#define ONES_H2 0x3C003C00u

__global__ __launch_bounds__(128, 2) void attn_mma(
    const int* __restrict__ um1, const int* __restrict__ um2)
{
    extern __shared__ char smem[];
    const uint32_t sb = smem_u32(smem);
    float* m2f = (float*)(smem + SMM2);

    const int tid = threadIdx.x;
    const int lane = tid & 31, wid = tid >> 5;
    const int g = lane >> 2, tig = lane & 3;
    const int b = blockIdx.z, h = blockIdx.y, qt = blockIdx.x;
    const int mbase = wid * 32;

    {
        const __half* src = g_KVh + (size_t)(b * SEQ) * DIM + h * HD;
        #pragma unroll
        for (int p = 0; p < 8; p++) {
            int row = (tid >> 3) + p * 16, ch = tid & 7;
            uint32_t dst = sb + SMK0 + SWZ((uint32_t)row * 128u + (uint32_t)ch * 16u);
            CP_ASYNC16(dst, src + (size_t)row * DIM + ch * 8);
        }
        CP_COMMIT();
        m2f[tid] = (um2[b * SEQ + tid] != 0) ? 0.0f : -1e30f;

        const __half* qs = g_Qh + (size_t)(b * SEQ + qt * QROWS) * DIM + h * HD;
        #pragma unroll
        for (int p = 0; p < 8; p++) {
            int row = (tid >> 3) + p * 16, ch = tid & 7;
            uint4 v = *(const uint4*)(qs + (size_t)row * DIM + ch * 8);
            *(uint4*)(smem + SMQ + SWZ((uint32_t)row * 128u + (uint32_t)ch * 16u)) = v;
        }
    }

    bool rv[2][2];
    #pragma unroll
    for (int m = 0; m < 2; m++)
        #pragma unroll
        for (int r = 0; r < 2; r++)
            rv[m][r] = um1[b * SEQ + qt * QROWS + mbase + m * 16 + r * 8 + g] != 0;

    const int matq = lane >> 3, rl = lane & 7;
    const uint32_t rsw = (uint32_t)rl << 4;
    const uint32_t row_bs = (uint32_t)(rl + ((matq & 2) ? 8 : 0)) * 128u;
    const uint32_t cl_bs  = (matq & 1) ? 16u : 0u;
    uint32_t bsk[4];
    #pragma unroll
    for (int kf = 0; kf < 4; kf++)
        bsk[kf] = sb + SMK0 + row_bs + (((uint32_t)kf * 32u + cl_bs) ^ rsw);
    const uint32_t row_bo = (uint32_t)(rl + ((matq & 1) ? 8 : 0)) * 128u;
    const uint32_t cl_bo  = (matq & 2) ? 16u : 0u;
    uint32_t bok[4];
    #pragma unroll
    for (int dp = 0; dp < 4; dp++)
        bok[dp] = sb + SMK0 + row_bo + (((uint32_t)dp * 32u + cl_bo) ^ rsw);

    __syncthreads();   // Q visible

    uint32_t qa[2][4][4];
    #pragma unroll
    for (int m = 0; m < 2; m++)
        #pragma unroll
        for (int kf = 0; kf < 4; kf++)
            LDSM_X4(qa[m][kf][0], qa[m][kf][1], qa[m][kf][2], qa[m][kf][3],
                    lm_a(sb + SMQ, lane, mbase + m * 16, kf * 16));

    float oc[2][8][4];
    #pragma unroll
    for (int m = 0; m < 2; m++)
        #pragma unroll
        for (int n = 0; n < 8; n++)
            #pragma unroll
            for (int k = 0; k < 4; k++) oc[m][n][k] = 0.f;
    float os[2][4];
    #pragma unroll
    for (int m = 0; m < 2; m++)
        #pragma unroll
        for (int k = 0; k < 4; k++) os[m][k] = 0.f;

    for (int kt = 0; kt < 16; kt++) {
        const int cur = kt & 1, nxt = cur ^ 1;
        if (kt < 15) {
            const __half* src =
                g_KVh + (size_t)(b * SEQ + (kt + 1) * 128) * DIM + h * HD;
            #pragma unroll
            for (int p = 0; p < 8; p++) {
                int row = (tid >> 3) + p * 16, ch = tid & 7;
                uint32_t dst = sb + SMK0 + (uint32_t)nxt * 16384u +
                               SWZ((uint32_t)row * 128u + (uint32_t)ch * 16u);
                CP_ASYNC16(dst, src + (size_t)row * DIM + ch * 8);
            }
            CP_COMMIT();
            m2f[nxt * 128 + tid] = (um2[b * SEQ + (kt + 1) * 128 + tid] != 0) ? 0.0f : -1e30f;
            CP_WAIT1();
        } else {
            CP_WAIT0();
        }
        __syncthreads();   // K[cur] + m2[cur] ready

        const uint32_t koff = (uint32_t)cur * 16384u;
        uint32_t bsc[4], boc[4];
        #pragma unroll
        for (int i = 0; i < 4; i++) { bsc[i] = bsk[i] + koff; boc[i] = bok[i] + koff; }
        const float* m2c = m2f + cur * 128 + 2 * tig;

        #pragma unroll
        for (int c4 = 0; c4 < 4; c4++) {
            float sc[2][4][4];
            #pragma unroll
            for (int m = 0; m < 2; m++)
                #pragma unroll
                for (int n = 0; n < 4; n++)
                    #pragma unroll
                    for (int k = 0; k < 4; k++) sc[m][n][k] = 0.f;

            #pragma unroll
            for (int np = 0; np < 2; np++) {
                const uint32_t roff = (uint32_t)(c4 * 32 + np * 16) * 128u;
                uint32_t bb[4][4];
                #pragma unroll
                for (int kf = 0; kf < 4; kf++)
                    LDSM_X4(bb[kf][0], bb[kf][1], bb[kf][2], bb[kf][3],
                            bsc[kf] + roff);
                #pragma unroll
                for (int m = 0; m < 2; m++)
                    #pragma unroll
                    for (int nt = 0; nt < 2; nt++)
                        #pragma unroll
                        for (int kf = 0; kf < 4; kf++)
                            mma_f16(sc[m][np * 2 + nt],
                                    qa[m][kf][0], qa[m][kf][1], qa[m][kf][2], qa[m][kf][3],
                                    bb[kf][nt * 2], bb[kf][nt * 2 + 1]);
            }

            uint32_t aP[2][2][4];
            #pragma unroll
            for (int m = 0; m < 2; m++) {
                #pragma unroll
                for (int n = 0; n < 4; n++) {
                    float2 mv = *(const float2*)&m2c[c4 * 32 + n * 8];
                    float x0 = sc[m][n][0] + mv.x;
                    float x1 = sc[m][n][1] + mv.y;
                    float x2 = sc[m][n][2] + mv.x;
                    float x3 = sc[m][n][3] + mv.y;
                    x0 = rv[m][0] ? x0 : 0.0f;
                    x1 = rv[m][0] ? x1 : 0.0f;
                    x2 = rv[m][1] ? x2 : 0.0f;
                    x3 = rv[m][1] ? x3 : 0.0f;
                    uint32_t plo = cvt_h2(x1, x0);
                    uint32_t phi = cvt_h2(x3, x2);
                    EX2_H2(plo, plo);
                    EX2_H2(phi, phi);
                    aP[m][n >> 1][(n & 1) * 2 + 0] = plo;
                    aP[m][n >> 1][(n & 1) * 2 + 1] = phi;
                }
            }

            #pragma unroll
            for (int kf = 0; kf < 2; kf++) {
                const uint32_t roff = (uint32_t)(c4 * 32 + kf * 16) * 128u;
                #pragma unroll
                for (int m = 0; m < 2; m++)
                    mma_f16(os[m], aP[m][kf][0], aP[m][kf][1],
                            aP[m][kf][2], aP[m][kf][3], ONES_H2, ONES_H2);
                #pragma unroll
                for (int dp = 0; dp < 4; dp++) {
                    uint32_t r0, r1, r2, r3;
                    LDSM_X4T(r0, r1, r2, r3, boc[dp] + roff);
                    #pragma unroll
                    for (int m = 0; m < 2; m++) {
                        mma_f16(oc[m][dp * 2],
                                aP[m][kf][0], aP[m][kf][1], aP[m][kf][2], aP[m][kf][3],
                                r0, r1);
                        mma_f16(oc[m][dp * 2 + 1],
                                aP[m][kf][0], aP[m][kf][1], aP[m][kf][2], aP[m][kf][3],
                                r2, r3);
                    }
                }
            }
        }
        __syncthreads();   // done reading K[cur] before overwrite
    }

    float* Og = g_A + (size_t)(b * SEQ + qt * QROWS) * DIM + h * HD;
    #pragma unroll
    for (int m = 0; m < 2; m++) {
        const float inv0 = 1.0f / os[m][0];
        const float inv1 = 1.0f / os[m][2];
        int row0 = mbase + m * 16 + g;
        #pragma unroll
        for (int dt = 0; dt < 8; dt++) {
            int col = dt * 8 + 2 * tig;
            *(float2*)(Og + (size_t)row0 * DIM + col) =
                make_float2(oc[m][dt][0] * inv0, oc[m][dt][1] * inv0);
            *(float2*)(Og + (size_t)(row0 + 8) * DIM + col) =
                make_float2(oc[m][dt][2] * inv1, oc[m][dt][3] * inv1);
        }
    }
}

// ---------------------------------------------------------------------------
// Epilogue: x = LN1(attn + modal1); out = LN2(attn + x).  (FFN is dead code.)
// ---------------------------------------------------------------------------
__global__ __launch_bounds__(128) void epilogue_kernel(
    const float* __restrict__ modal1,
    const float* __restrict__ g1, const float* __restrict__ b1,
    const float* __restrict__ g2, const float* __restrict__ b2,
    float* __restrict__ out)
{
    __shared__ float red[2][4];
    const int row = blockIdx.x;
    const int t = threadIdx.x;
    const int lane = t & 31, wid = t >> 5;

    const float4 av = ((const float4*)(g_A    + (size_t)row * DIM))[t];
    const float4 mv = ((const float4*)(modal1 + (size_t)row * DIM))[t];
    float x[4] = {av.x + mv.x, av.y + mv.y, av.z + mv.z, av.w + mv.w};

    float s = x[0] + x[1] + x[2] + x[3];
    float q = x[0]*x[0] + x[1]*x[1] + x[2]*x[2] + x[3]*x[3];
    #pragma unroll
    for (int off = 16; off > 0; off >>= 1) {
        s += __shfl_xor_sync(0xffffffffu, s, off);
        q += __shfl_xor_sync(0xffffffffu, q, off);
    }
    if (lane == 0) { red[0][wid] = s; red[1][wid] = q; }
    __syncthreads();
    s = red[0][0] + red[0][1] + red[0][2] + red[0][3];
    q = red[1][0] + red[1][1] + red[1][2] + red[1][3];
    float mean = s * (1.0f / 512.0f);
    float var  = q * (1.0f / 512.0f) - mean * mean;
    float rstd = rsqrtf(var + 1e-5f);

    const float4 g1f = ((const float4*)g1)[t];
    const float4 b1f = ((const float4*)b1)[t];
    float y[4];
    y[0] = av.x + ((x[0] - mean) * rstd * g1f.x + b1f.x);
    y[1] = av.y + ((x[1] - mean) * rstd * g1f.y + b1f.y);
    y[2] = av.z + ((x[2] - mean) * rstd * g1f.z + b1f.z);
    y[3] = av.w + ((x[3] - mean) * rstd * g1f.w + b1f.w);

    __syncthreads();
    s = y[0] + y[1] + y[2] + y[3];
    q = y[0]*y[0] + y[1]*y[1] + y[2]*y[2] + y[3]*y[3];
    #pragma unroll
    for (int off = 16; off > 0; off >>= 1) {
        s += __shfl_xor_sync(0xffffffffu, s, off);
        q += __shfl_xor_sync(0xffffffffu, q, off);
    }
    if (lane == 0) { red[0][wid] = s; red[1][wid] = q; }
    __syncthreads();
    s = red[0][0] + red[0][1] + red[0][2] + red[0][3];
    q = red[1][0] + red[1][1] + red[1][2] + red[1][3];
    float mean2 = s * (1.0f / 512.0f);
    float var2  = q * (1.0f / 512.0f) - mean2 * mean2;
    float rstd2 = rsqrtf(var2 + 1e-5f);

    const float4 g2f = ((const float4*)g2)[t];
    const float4 b2f = ((const float4*)b2)[t];
    float4 ov = make_float4((y[0] - mean2) * rstd2 * g2f.x + b2f.x,
                            (y[1] - mean2) * rstd2 * g2f.y + b2f.y,
                            (y[2] - mean2) * rstd2 * g2f.z + b2f.z,
                            (y[3] - mean2) * rstd2 * g2f.w + b2f.w);
    ((float4*)(out + (size_t)row * DIM))[t] = ov;
}

// ---------------------------------------------------------------------------
extern "C" void kernel_launch(void* const* d_in, const int* in_sizes, int n_in,
                              void* d_out, int out_size)
{
    const float* modal1 = (const float*)d_in[0];
    const float* modal2 = (const float*)d_in[1];
    const int*   um1    = (const int*)  d_in[2];
    const int*   um2    = (const int*)  d_in[3];
    const float* Wq     = (const float*)d_in[4];
    const float* bq     = (const float*)d_in[5];
    const float* Wkv    = (const float*)d_in[6];
    const float* bkv    = (const float*)d_in[7];
    const float* ln1g   = (const float*)d_in[8];
    const float* ln1b   = (const float*)d_in[9];
    // d_in[10..13] = W1,b1,W2,b2 -> FFN output is discarded by the reference.
    const float* ln2g   = (const float*)d_in[14];
    const float* ln2b   = (const float*)d_in[15];
    float* out = (float*)d_out;

    cudaFuncSetAttribute(gemm_tc,
                         cudaFuncAttributeMaxDynamicSharedMemorySize, GEMM_SMEM);
    cudaFuncSetAttribute(attn_mma,
                         cudaFuncAttributeMaxDynamicSharedMemorySize, ATT_SMEM);

    dim3 gw(16, 16, 2);
    convert_wt<<<gw, dim3(32, 8)>>>(Wq, Wkv);

    dim3 gg(DIM / 128, (BSZ * SEQ) / 128, 2);
    gemm_tc<<<gg, 256, GEMM_SMEM>>>(modal1, modal2, bq, bkv);

    dim3 ga(SEQ / QROWS, NHEAD, BSZ);
    attn_mma<<<ga, 128, ATT_SMEM>>>(um1, um2);

    epilogue_kernel<<<BSZ * SEQ, 128>>>(modal1, ln1g, ln1b, ln2g, ln2b, out);
}

// round 15
// speedup vs baseline: 1.1248x; 1.0098x over previous
#include <cuda_runtime.h>
#include <cuda_fp16.h>
#include <cstdint>
#include <math.h>

#define BSZ 4
#define SEQ 2048
#define DIM 512
#define NHEAD 8
#define HD 64
#define ATT_SCALE 0.044194173824159216f        // 1/sqrt(512)
#define EXC (ATT_SCALE * 1.4426950408889634f)  // scale * log2(e)

// ---------------------------------------------------------------------------
// Scratch (static device globals: allocation-free)
// ---------------------------------------------------------------------------
__device__ __half g_Wqt [DIM*DIM];   // transposed [n][k]
__device__ __half g_Wkvt[DIM*DIM];   // transposed [n][k]
__device__ __half g_Qh [BSZ*SEQ*DIM];   // pre-scaled by EXC
__device__ __half g_KVh[BSZ*SEQ*DIM];
__device__ __half g_A  [BSZ*SEQ*DIM];   // attention output, fp16

// ---------------------------------------------------------------------------
// Baseline-PTX helpers (compute_80 features only: mma.sync / ldmatrix / cp.async)
// ---------------------------------------------------------------------------
__device__ __forceinline__ uint32_t smem_u32(const void* p) {
    uint32_t a;
    asm("{ .reg .u64 t; cvta.to.shared.u64 t, %1; cvt.u32.u64 %0, t; }" : "=r"(a) : "l"(p));
    return a;
}
#define SWZ(off) ((off) ^ (((off) >> 3) & 0x70))

#define LDSM_X4(r0,r1,r2,r3,a) \
    asm volatile("ldmatrix.sync.aligned.m8n8.x4.shared.b16 {%0,%1,%2,%3}, [%4];" \
        : "=r"(r0),"=r"(r1),"=r"(r2),"=r"(r3) : "r"(a))
#define LDSM_X4T(r0,r1,r2,r3,a) \
    asm volatile("ldmatrix.sync.aligned.m8n8.x4.trans.shared.b16 {%0,%1,%2,%3}, [%4];" \
        : "=r"(r0),"=r"(r1),"=r"(r2),"=r"(r3) : "r"(a))

__device__ __forceinline__ void mma_f16(float c[4], uint32_t a0, uint32_t a1,
                                        uint32_t a2, uint32_t a3,
                                        uint32_t b0, uint32_t b1) {
    asm volatile(
        "mma.sync.aligned.m16n8k16.row.col.f32.f16.f16.f32 "
        "{%0,%1,%2,%3}, {%4,%5,%6,%7}, {%8,%9}, {%0,%1,%2,%3};"
        : "+f"(c[0]), "+f"(c[1]), "+f"(c[2]), "+f"(c[3])
        : "r"(a0), "r"(a1), "r"(a2), "r"(a3), "r"(b0), "r"(b1));
}

#define CP_ASYNC16(dst, src) \
    asm volatile("cp.async.cg.shared.global [%0], [%1], 16;" :: "r"(dst), "l"(src))
#define CP_COMMIT() asm volatile("cp.async.commit_group;" ::: "memory")
#define CP_WAIT1()  asm volatile("cp.async.wait_group 1;" ::: "memory")
#define CP_WAIT0()  asm volatile("cp.async.wait_group 0;" ::: "memory")

__device__ __forceinline__ uint32_t cvt_h2(float hi, float lo) {
    uint32_t r;
    asm("cvt.rn.f16x2.f32 %0, %1, %2;" : "=r"(r) : "f"(hi), "f"(lo));
    return r;
}
#define EX2_H2(d, a) asm("ex2.approx.f16x2 %0, %1;" : "=r"(d) : "r"(a))

// ldmatrix address builders (row stride 128B, SW128 swizzle) — prologue only
__device__ __forceinline__ uint32_t lm_a(uint32_t base, int lane, int m0, int k0) {
    int mat = lane >> 3, r = lane & 7;
    int row = m0 + r + ((mat & 1) ? 8 : 0);
    int colb = (k0 + ((mat & 2) ? 8 : 0)) * 2;
    uint32_t off = (uint32_t)row * 128u + (uint32_t)colb;
    return base + SWZ(off);
}
__device__ __forceinline__ uint32_t lm_bs(uint32_t base, int lane, int n0, int k0) {
    int mat = lane >> 3, r = lane & 7;
    int row = n0 + r + ((mat & 2) ? 8 : 0);
    int colb = (k0 + ((mat & 1) ? 8 : 0)) * 2;
    uint32_t off = (uint32_t)row * 128u + (uint32_t)colb;
    return base + SWZ(off);
}

// ---------------------------------------------------------------------------
// Convert + transpose W (512x512): Wt[n][k] = W[k][n], fp16 out.
// ---------------------------------------------------------------------------
__global__ __launch_bounds__(256) void convert_wt(
    const float* __restrict__ Wq, const float* __restrict__ Wkv)
{
    __shared__ float t[32][33];
    const float* W = blockIdx.z ? Wkv : Wq;
    __half* Wt = blockIdx.z ? g_Wkvt : g_Wqt;
    int k0 = blockIdx.x * 32, n0 = blockIdx.y * 32;
    int tx = threadIdx.x, ty = threadIdx.y;
    #pragma unroll
    for (int i = 0; i < 4; i++)
        t[ty + 8 * i][tx] = W[(size_t)(k0 + ty + 8 * i) * DIM + n0 + tx];
    __syncthreads();
    #pragma unroll
    for (int i = 0; i < 4; i++)
        Wt[(size_t)(n0 + ty + 8 * i) * DIM + k0 + tx] =
            __float2half(t[tx][ty + 8 * i]);
}

// ---------------------------------------------------------------------------
// Tensor-core projection GEMM: C(8192x512) = A(fp32) @ W + bias, fp16 out.
// Fused fp32->fp16 A conversion (LDG.128 -> cvt -> STS, reg double-buffered).
// Q output (blockIdx.z==0) is PRE-SCALED by EXC for the attention softmax.
// ---------------------------------------------------------------------------
#define GSM_A0 0
#define GSM_B0 16384
#define GSM_A1 32768
#define GSM_B1 49152
#define GEMM_SMEM 65536

__global__ __launch_bounds__(256) void gemm_tc(
    const float* __restrict__ M1, const float* __restrict__ M2,
    const float* __restrict__ bq, const float* __restrict__ bkv)
{
    extern __shared__ char smem[];
    const uint32_t sb = smem_u32(smem);

    const float* A32; const __half* Wt;
    const float* bias; __half* C;
    if (blockIdx.z == 0) { A32 = M1; Wt = g_Wqt;  bias = bq;  C = g_Qh;  }
    else                 { A32 = M2; Wt = g_Wkvt; bias = bkv; C = g_KVh; }
    const float escale = (blockIdx.z == 0) ? EXC : 1.0f;

    const int tid = threadIdx.x;
    const int lane = tid & 31, wid = tid >> 5;
    const int g = lane >> 2, tig = lane & 3;
    const int wm = wid & 1, wn = wid >> 1;
    const int m0 = blockIdx.y * 128, n0 = blockIdx.x * 128;

    const int lrow = tid >> 3, lch = tid & 7;

    const float* Ab = A32 + (size_t)(m0 + lrow) * DIM + lch * 8;
    uint32_t asw[4];
    #pragma unroll
    for (int p = 0; p < 4; p++)
        asw[p] = SWZ((uint32_t)(lrow + p * 32) * 128u + (uint32_t)lch * 16u);

    float4 pre[4][2];

    {
        const __half* Bs = Wt + (size_t)(n0 + lrow) * DIM + lch * 8;
        #pragma unroll
        for (int p = 0; p < 4; p++)
            CP_ASYNC16(sb + GSM_B0 + asw[p], Bs + (size_t)p * 32 * DIM);
        CP_COMMIT();
        #pragma unroll
        for (int p = 0; p < 4; p++) {
            pre[p][0] = *(const float4*)(Ab + (size_t)p * 32 * DIM);
            pre[p][1] = *(const float4*)(Ab + (size_t)p * 32 * DIM + 4);
        }
        #pragma unroll
        for (int p = 0; p < 4; p++) {
            uint4 w = make_uint4(cvt_h2(pre[p][0].y, pre[p][0].x),
                                 cvt_h2(pre[p][0].w, pre[p][0].z),
                                 cvt_h2(pre[p][1].y, pre[p][1].x),
                                 cvt_h2(pre[p][1].w, pre[p][1].z));
            *(uint4*)(smem + GSM_A0 + asw[p]) = w;
        }
        CP_WAIT0();
    }
    __syncthreads();

    float acc[4][4][4];
    #pragma unroll
    for (int m = 0; m < 4; m++)
        #pragma unroll
        for (int n = 0; n < 4; n++)
            #pragma unroll
            for (int k = 0; k < 4; k++) acc[m][n][k] = 0.f;

    for (int kt = 0; kt < 8; kt++) {
        const int cur = kt & 1, nxt = cur ^ 1;
        if (kt < 7) {
            const float* An = Ab + (kt + 1) * 64;
            #pragma unroll
            for (int p = 0; p < 4; p++) {
                pre[p][0] = *(const float4*)(An + (size_t)p * 32 * DIM);
                pre[p][1] = *(const float4*)(An + (size_t)p * 32 * DIM + 4);
            }
            const __half* Bs = Wt + (size_t)(n0 + lrow) * DIM + (kt + 1) * 64 + lch * 8;
            const uint32_t bb = sb + (nxt ? GSM_B1 : GSM_B0);
            #pragma unroll
            for (int p = 0; p < 4; p++)
                CP_ASYNC16(bb + asw[p], Bs + (size_t)p * 32 * DIM);
            CP_COMMIT();
        }

        const uint32_t abase = sb + (cur ? GSM_A1 : GSM_A0);
        const uint32_t bbase = sb + (cur ? GSM_B1 : GSM_B0);

        #pragma unroll
        for (int kf = 0; kf < 4; kf++) {
            uint32_t qa[4][4];
            #pragma unroll
            for (int m = 0; m < 4; m++)
                LDSM_X4(qa[m][0], qa[m][1], qa[m][2], qa[m][3],
                        lm_a(abase, lane, wm * 64 + m * 16, kf * 16));
            uint32_t bb[2][4];
            #pragma unroll
            for (int np = 0; np < 2; np++)
                LDSM_X4(bb[np][0], bb[np][1], bb[np][2], bb[np][3],
                        lm_bs(bbase, lane, wn * 32 + np * 16, kf * 16));
            #pragma unroll
            for (int m = 0; m < 4; m++)
                #pragma unroll
                for (int np = 0; np < 2; np++)
                    #pragma unroll
                    for (int nt = 0; nt < 2; nt++)
                        mma_f16(acc[m][np * 2 + nt],
                                qa[m][0], qa[m][1], qa[m][2], qa[m][3],
                                bb[np][nt * 2], bb[np][nt * 2 + 1]);
        }

        if (kt < 7) {
            const uint32_t ab = sb + (nxt ? GSM_A1 : GSM_A0);
            #pragma unroll
            for (int p = 0; p < 4; p++) {
                uint4 w = make_uint4(cvt_h2(pre[p][0].y, pre[p][0].x),
                                     cvt_h2(pre[p][0].w, pre[p][0].z),
                                     cvt_h2(pre[p][1].y, pre[p][1].x),
                                     cvt_h2(pre[p][1].w, pre[p][1].z));
                *(uint4*)(smem + (ab - sb) + asw[p]) = w;
            }
            CP_WAIT0();
        }
        __syncthreads();
    }

    float2 bf[4];
    #pragma unroll
    for (int n = 0; n < 4; n++)
        bf[n] = *(const float2*)&bias[n0 + wn * 32 + n * 8 + 2 * tig];

    #pragma unroll
    for (int m = 0; m < 4; m++) {
        int row = m0 + wm * 64 + m * 16 + g;
        #pragma unroll
        for (int n = 0; n < 4; n++) {
            int col = n0 + wn * 32 + n * 8 + 2 * tig;
            *(uint32_t*)(C + (size_t)row * DIM + col) =
                cvt_h2((acc[m][n][1] + bf[n].y) * escale,
                       (acc[m][n][0] + bf[n].x) * escale);
            *(uint32_t*)(C + (size_t)(row + 8) * DIM + col) =
                cvt_h2((acc[m][n][3] + bf[n].y) * escale,
                       (acc[m][n][2] + bf[n].x) * escale);
        }
    }
}

// ---------------------------------------------------------------------------
// fp16 mma.sync flash attention.
// 128 threads / 4 warps, 32 q-rows/warp, 2 CTAs/SM.
// THIS ROUND: S-phase mma loop reordered (kf OUTER -> 4 independent
// accumulators between touches, breaking the 4-long dependent HMMA chains);
// O-phase LDSM_X4T loads hoisted ahead of the mma burst; fp16 g_A store.
// ---------------------------------------------------------------------------
#define QROWS 128
#define SMQ   0
#define SMK0  16384
#define SMM2  49152
#define ATT_SMEM (49152 + 2 * 128 * 4)
#define ONES_H2 0x3C003C00u

__global__ __launch_bounds__(128, 2) void attn_mma(
    const int* __restrict__ um1, const int* __restrict__ um2)
{
    extern __shared__ char smem[];
    const uint32_t sb = smem_u32(smem);
    float* m2f = (float*)(smem + SMM2);

    const int tid = threadIdx.x;
    const int lane = tid & 31, wid = tid >> 5;
    const int g = lane >> 2, tig = lane & 3;
    const int b = blockIdx.z, h = blockIdx.y, qt = blockIdx.x;
    const int mbase = wid * 32;

    {
        const __half* src = g_KVh + (size_t)(b * SEQ) * DIM + h * HD;
        #pragma unroll
        for (int p = 0; p < 8; p++) {
            int row = (tid >> 3) + p * 16, ch = tid & 7;
            uint32_t dst = sb + SMK0 + SWZ((uint32_t)row * 128u + (uint32_t)ch * 16u);
            CP_ASYNC16(dst, src + (size_t)row * DIM + ch * 8);
        }
        CP_COMMIT();
        m2f[tid] = (um2[b * SEQ + tid] != 0) ? 0.0f : -1e30f;

        const __half* qs = g_Qh + (size_t)(b * SEQ + qt * QROWS) * DIM + h * HD;
        #pragma unroll
        for (int p = 0; p < 8; p++) {
            int row = (tid >> 3) + p * 16, ch = tid & 7;
            uint4 v = *(const uint4*)(qs + (size_t)row * DIM + ch * 8);
            *(uint4*)(smem + SMQ + SWZ((uint32_t)row * 128u + (uint32_t)ch * 16u)) = v;
        }
    }

    bool rv[2][2];
    #pragma unroll
    for (int m = 0; m < 2; m++)
        #pragma unroll
        for (int r = 0; r < 2; r++)
            rv[m][r] = um1[b * SEQ + qt * QROWS + mbase + m * 16 + r * 8 + g] != 0;

    const int matq = lane >> 3, rl = lane & 7;
    const uint32_t rsw = (uint32_t)rl << 4;
    const uint32_t row_bs = (uint32_t)(rl + ((matq & 2) ? 8 : 0)) * 128u;
    const uint32_t cl_bs  = (matq & 1) ? 16u : 0u;
    uint32_t bsk[4];
    #pragma unroll
    for (int kf = 0; kf < 4; kf++)
        bsk[kf] = sb + SMK0 + row_bs + (((uint32_t)kf * 32u + cl_bs) ^ rsw);
    const uint32_t row_bo = (uint32_t)(rl + ((matq & 1) ? 8 : 0)) * 128u;
    const uint32_t cl_bo  = (matq & 2) ? 16u : 0u;
    uint32_t bok[4];
    #pragma unroll
    for (int dp = 0; dp < 4; dp++)
        bok[dp] = sb + SMK0 + row_bo + (((uint32_t)dp * 32u + cl_bo) ^ rsw);

    __syncthreads();   // Q visible

    uint32_t qa[2][4][4];
    #pragma unroll
    for (int m = 0; m < 2; m++)
        #pragma unroll
        for (int kf = 0; kf < 4; kf++)
            LDSM_X4(qa[m][kf][0], qa[m][kf][1], qa[m][kf][2], qa[m][kf][3],
                    lm_a(sb + SMQ, lane, mbase + m * 16, kf * 16));

    float oc[2][8][4];
    #pragma unroll
    for (int m = 0; m < 2; m++)
        #pragma unroll
        for (int n = 0; n < 8; n++)
            #pragma unroll
            for (int k = 0; k < 4; k++) oc[m][n][k] = 0.f;
    float os[2][4];
    #pragma unroll
    for (int m = 0; m < 2; m++)
        #pragma unroll
        for (int k = 0; k < 4; k++) os[m][k] = 0.f;

    for (int kt = 0; kt < 16; kt++) {
        const int cur = kt & 1, nxt = cur ^ 1;
        if (kt < 15) {
            const __half* src =
                g_KVh + (size_t)(b * SEQ + (kt + 1) * 128) * DIM + h * HD;
            #pragma unroll
            for (int p = 0; p < 8; p++) {
                int row = (tid >> 3) + p * 16, ch = tid & 7;
                uint32_t dst = sb + SMK0 + (uint32_t)nxt * 16384u +
                               SWZ((uint32_t)row * 128u + (uint32_t)ch * 16u);
                CP_ASYNC16(dst, src + (size_t)row * DIM + ch * 8);
            }
            CP_COMMIT();
            m2f[nxt * 128 + tid] = (um2[b * SEQ + (kt + 1) * 128 + tid] != 0) ? 0.0f : -1e30f;
            CP_WAIT1();
        } else {
            CP_WAIT0();
        }
        __syncthreads();   // K[cur] + m2[cur] ready

        const uint32_t koff = (uint32_t)cur * 16384u;
        uint32_t bsc[4], boc[4];
        #pragma unroll
        for (int i = 0; i < 4; i++) { bsc[i] = bsk[i] + koff; boc[i] = bok[i] + koff; }
        const float* m2c = m2f + cur * 128 + 2 * tig;

        #pragma unroll
        for (int c4 = 0; c4 < 4; c4++) {
            // ---- S chunk: 32 keys x 2 m-tiles (kf-outer: no dep chains) ----
            float sc[2][4][4];
            #pragma unroll
            for (int m = 0; m < 2; m++)
                #pragma unroll
                for (int n = 0; n < 4; n++)
                    #pragma unroll
                    for (int k = 0; k < 4; k++) sc[m][n][k] = 0.f;

            #pragma unroll
            for (int np = 0; np < 2; np++) {
                const uint32_t roff = (uint32_t)(c4 * 32 + np * 16) * 128u;
                uint32_t bb[4][4];
                #pragma unroll
                for (int kf = 0; kf < 4; kf++)
                    LDSM_X4(bb[kf][0], bb[kf][1], bb[kf][2], bb[kf][3],
                            bsc[kf] + roff);
                #pragma unroll
                for (int kf = 0; kf < 4; kf++)
                    #pragma unroll
                    for (int m = 0; m < 2; m++)
                        #pragma unroll
                        for (int nt = 0; nt < 2; nt++)
                            mma_f16(sc[m][np * 2 + nt],
                                    qa[m][kf][0], qa[m][kf][1], qa[m][kf][2], qa[m][kf][3],
                                    bb[kf][nt * 2], bb[kf][nt * 2 + 1]);
            }

            // ---- softmax: masked add -> f16x2 pack -> ex2.f16x2 ----
            uint32_t aP[2][2][4];
            #pragma unroll
            for (int m = 0; m < 2; m++) {
                #pragma unroll
                for (int n = 0; n < 4; n++) {
                    float2 mv = *(const float2*)&m2c[c4 * 32 + n * 8];
                    float x0 = sc[m][n][0] + mv.x;
                    float x1 = sc[m][n][1] + mv.y;
                    float x2 = sc[m][n][2] + mv.x;
                    float x3 = sc[m][n][3] + mv.y;
                    x0 = rv[m][0] ? x0 : 0.0f;
                    x1 = rv[m][0] ? x1 : 0.0f;
                    x2 = rv[m][1] ? x2 : 0.0f;
                    x3 = rv[m][1] ? x3 : 0.0f;
                    uint32_t plo = cvt_h2(x1, x0);
                    uint32_t phi = cvt_h2(x3, x2);
                    EX2_H2(plo, plo);
                    EX2_H2(phi, phi);
                    aP[m][n >> 1][(n & 1) * 2 + 0] = plo;
                    aP[m][n >> 1][(n & 1) * 2 + 1] = phi;
                }
            }

            // ---- O += P @ K (V = K); hoisted B-frag loads ----
            #pragma unroll
            for (int kf = 0; kf < 2; kf++) {
                const uint32_t roff = (uint32_t)(c4 * 32 + kf * 16) * 128u;
                uint32_t bo[4][4];
                #pragma unroll
                for (int dp = 0; dp < 4; dp++)
                    LDSM_X4T(bo[dp][0], bo[dp][1], bo[dp][2], bo[dp][3],
                             boc[dp] + roff);
                #pragma unroll
                for (int m = 0; m < 2; m++)
                    mma_f16(os[m], aP[m][kf][0], aP[m][kf][1],
                            aP[m][kf][2], aP[m][kf][3], ONES_H2, ONES_H2);
                #pragma unroll
                for (int dp = 0; dp < 4; dp++)
                    #pragma unroll
                    for (int m = 0; m < 2; m++) {
                        mma_f16(oc[m][dp * 2],
                                aP[m][kf][0], aP[m][kf][1], aP[m][kf][2], aP[m][kf][3],
                                bo[dp][0], bo[dp][1]);
                        mma_f16(oc[m][dp * 2 + 1],
                                aP[m][kf][0], aP[m][kf][1], aP[m][kf][2], aP[m][kf][3],
                                bo[dp][2], bo[dp][3]);
                    }
            }
        }
        __syncthreads();   // done reading K[cur] before overwrite
    }

    // ---- finalize (fp16 store) ----
    __half* Og = g_A + (size_t)(b * SEQ + qt * QROWS) * DIM + h * HD;
    #pragma unroll
    for (int m = 0; m < 2; m++) {
        const float inv0 = 1.0f / os[m][0];
        const float inv1 = 1.0f / os[m][2];
        int row0 = mbase + m * 16 + g;
        #pragma unroll
        for (int dt = 0; dt < 8; dt++) {
            int col = dt * 8 + 2 * tig;
            *(uint32_t*)(Og + (size_t)row0 * DIM + col) =
                cvt_h2(oc[m][dt][1] * inv0, oc[m][dt][0] * inv0);
            *(uint32_t*)(Og + (size_t)(row0 + 8) * DIM + col) =
                cvt_h2(oc[m][dt][3] * inv1, oc[m][dt][2] * inv1);
        }
    }
}

// ---------------------------------------------------------------------------
// Epilogue: x = LN1(attn + modal1); out = LN2(attn + x).  g_A is fp16.
// ---------------------------------------------------------------------------
__global__ __launch_bounds__(128) void epilogue_kernel(
    const float* __restrict__ modal1,
    const float* __restrict__ g1, const float* __restrict__ b1,
    const float* __restrict__ g2, const float* __restrict__ b2,
    float* __restrict__ out)
{
    __shared__ float red[2][4];
    const int row = blockIdx.x;
    const int t = threadIdx.x;
    const int lane = t & 31, wid = t >> 5;

    const uint2 ah = ((const uint2*)(g_A + (size_t)row * DIM))[t];
    float2 a01 = __half22float2(*(const __half2*)&ah.x);
    float2 a23 = __half22float2(*(const __half2*)&ah.y);
    float av[4] = {a01.x, a01.y, a23.x, a23.y};
    const float4 mv = ((const float4*)(modal1 + (size_t)row * DIM))[t];
    float x[4] = {av[0] + mv.x, av[1] + mv.y, av[2] + mv.z, av[3] + mv.w};

    float s = x[0] + x[1] + x[2] + x[3];
    float q = x[0]*x[0] + x[1]*x[1] + x[2]*x[2] + x[3]*x[3];
    #pragma unroll
    for (int off = 16; off > 0; off >>= 1) {
        s += __shfl_xor_sync(0xffffffffu, s, off);
        q += __shfl_xor_sync(0xffffffffu, q, off);
    }
    if (lane == 0) { red[0][wid] = s; red[1][wid] = q; }
    __syncthreads();
    s = red[0][0] + red[0][1] + red[0][2] + red[0][3];
    q = red[1][0] + red[1][1] + red[1][2] + red[1][3];
    float mean = s * (1.0f / 512.0f);
    float var  = q * (1.0f / 512.0f) - mean * mean;
    float rstd = rsqrtf(var + 1e-5f);

    const float4 g1f = ((const float4*)g1)[t];
    const float4 b1f = ((const float4*)b1)[t];
    float y[4];
    y[0] = av[0] + ((x[0] - mean) * rstd * g1f.x + b1f.x);
    y[1] = av[1] + ((x[1] - mean) * rstd * g1f.y + b1f.y);
    y[2] = av[2] + ((x[2] - mean) * rstd * g1f.z + b1f.z);
    y[3] = av[3] + ((x[3] - mean) * rstd * g1f.w + b1f.w);

    __syncthreads();
    s = y[0] + y[1] + y[2] + y[3];
    q = y[0]*y[0] + y[1]*y[1] + y[2]*y[2] + y[3]*y[3];
    #pragma unroll
    for (int off = 16; off > 0; off >>= 1) {
        s += __shfl_xor_sync(0xffffffffu, s, off);
        q += __shfl_xor_sync(0xffffffffu, q, off);
    }
    if (lane == 0) { red[0][wid] = s; red[1][wid] = q; }
    __syncthreads();
    s = red[0][0] + red[0][1] + red[0][2] + red[0][3];
    q = red[1][0] + red[1][1] + red[1][2] + red[1][3];
    float mean2 = s * (1.0f / 512.0f);
    float var2  = q * (1.0f / 512.0f) - mean2 * mean2;
    float rstd2 = rsqrtf(var2 + 1e-5f);

    const float4 g2f = ((const float4*)g2)[t];
    const float4 b2f = ((const float4*)b2)[t];
    float4 ov = make_float4((y[0] - mean2) * rstd2 * g2f.x + b2f.x,
                            (y[1] - mean2) * rstd2 * g2f.y + b2f.y,
                            (y[2] - mean2) * rstd2 * g2f.z + b2f.z,
                            (y[3] - mean2) * rstd2 * g2f.w + b2f.w);
    ((float4*)(out + (size_t)row * DIM))[t] = ov;
}

// ---------------------------------------------------------------------------
extern "C" void kernel_launch(void* const* d_in, const int* in_sizes, int n_in,
                              void* d_out, int out_size)
{
    const float* modal1 = (const float*)d_in[0];
    const float* modal2 = (const float*)d_in[1];
    const int*   um1    = (const int*)  d_in[2];
    const int*   um2    = (const int*)  d_in[3];
    const float* Wq     = (const float*)d_in[4];
    const float* bq     = (const float*)d_in[5];
    const float* Wkv    = (const float*)d_in[6];
    const float* bkv    = (const float*)d_in[7];
    const float* ln1g   = (const float*)d_in[8];
    const float* ln1b   = (const float*)d_in[9];
    // d_in[10..13] = W1,b1,W2,b2 -> FFN output is discarded by the reference.
    const float* ln2g   = (const float*)d_in[14];
    const float* ln2b   = (const float*)d_in[15];
    float* out = (float*)d_out;

    cudaFuncSetAttribute(gemm_tc,
                         cudaFuncAttributeMaxDynamicSharedMemorySize, GEMM_SMEM);
    cudaFuncSetAttribute(attn_mma,
                         cudaFuncAttributeMaxDynamicSharedMemorySize, ATT_SMEM);

    dim3 gw(16, 16, 2);
    convert_wt<<<gw, dim3(32, 8)>>>(Wq, Wkv);

    dim3 gg(DIM / 128, (BSZ * SEQ) / 128, 2);
    gemm_tc<<<gg, 256, GEMM_SMEM>>>(modal1, modal2, bq, bkv);

    dim3 ga(SEQ / QROWS, NHEAD, BSZ);
    attn_mma<<<ga, 128, ATT_SMEM>>>(um1, um2);

    epilogue_kernel<<<BSZ * SEQ, 128>>>(modal1, ln1g, ln1b, ln2g, ln2b, out);
}

// round 16
// speedup vs baseline: 1.1405x; 1.0140x over previous
#include <cuda_runtime.h>
#include <cuda_fp16.h>
#include <cstdint>
#include <math.h>

#define BSZ 4
#define SEQ 2048
#define DIM 512
#define NHEAD 8
#define HD 64
#define ATT_SCALE 0.044194173824159216f        // 1/sqrt(512)
#define EXC (ATT_SCALE * 1.4426950408889634f)  // scale * log2(e)

// ---------------------------------------------------------------------------
// Scratch (static device globals: allocation-free)
// ---------------------------------------------------------------------------
__device__ __half g_Wqt [DIM*DIM];   // transposed [n][k]
__device__ __half g_Wkvt[DIM*DIM];   // transposed [n][k]
__device__ __half g_Qh [BSZ*SEQ*DIM];   // pre-scaled by EXC
__device__ __half g_KVh[BSZ*SEQ*DIM];
__device__ __half g_A  [BSZ*SEQ*DIM];   // attention output, fp16

// ---------------------------------------------------------------------------
// Baseline-PTX helpers (compute_80 features only: mma.sync / ldmatrix / cp.async)
// ---------------------------------------------------------------------------
__device__ __forceinline__ uint32_t smem_u32(const void* p) {
    uint32_t a;
    asm("{ .reg .u64 t; cvta.to.shared.u64 t, %1; cvt.u32.u64 %0, t; }" : "=r"(a) : "l"(p));
    return a;
}
#define SWZ(off) ((off) ^ (((off) >> 3) & 0x70))

#define LDSM_X4(r0,r1,r2,r3,a) \
    asm volatile("ldmatrix.sync.aligned.m8n8.x4.shared.b16 {%0,%1,%2,%3}, [%4];" \
        : "=r"(r0),"=r"(r1),"=r"(r2),"=r"(r3) : "r"(a))
#define LDSM_X4T(r0,r1,r2,r3,a) \
    asm volatile("ldmatrix.sync.aligned.m8n8.x4.trans.shared.b16 {%0,%1,%2,%3}, [%4];" \
        : "=r"(r0),"=r"(r1),"=r"(r2),"=r"(r3) : "r"(a))

__device__ __forceinline__ void mma_f16(float c[4], uint32_t a0, uint32_t a1,
                                        uint32_t a2, uint32_t a3,
                                        uint32_t b0, uint32_t b1) {
    asm volatile(
        "mma.sync.aligned.m16n8k16.row.col.f32.f16.f16.f32 "
        "{%0,%1,%2,%3}, {%4,%5,%6,%7}, {%8,%9}, {%0,%1,%2,%3};"
        : "+f"(c[0]), "+f"(c[1]), "+f"(c[2]), "+f"(c[3])
        : "r"(a0), "r"(a1), "r"(a2), "r"(a3), "r"(b0), "r"(b1));
}

#define CP_ASYNC16(dst, src) \
    asm volatile("cp.async.cg.shared.global [%0], [%1], 16;" :: "r"(dst), "l"(src))
#define CP_COMMIT() asm volatile("cp.async.commit_group;" ::: "memory")
#define CP_WAIT1()  asm volatile("cp.async.wait_group 1;" ::: "memory")
#define CP_WAIT0()  asm volatile("cp.async.wait_group 0;" ::: "memory")

__device__ __forceinline__ uint32_t cvt_h2(float hi, float lo) {
    uint32_t r;
    asm("cvt.rn.f16x2.f32 %0, %1, %2;" : "=r"(r) : "f"(hi), "f"(lo));
    return r;
}
#define EX2_H2(d, a) asm("ex2.approx.f16x2 %0, %1;" : "=r"(d) : "r"(a))

// ldmatrix address builders (row stride 128B, SW128 swizzle) — prologue only
__device__ __forceinline__ uint32_t lm_a(uint32_t base, int lane, int m0, int k0) {
    int mat = lane >> 3, r = lane & 7;
    int row = m0 + r + ((mat & 1) ? 8 : 0);
    int colb = (k0 + ((mat & 2) ? 8 : 0)) * 2;
    uint32_t off = (uint32_t)row * 128u + (uint32_t)colb;
    return base + SWZ(off);
}
__device__ __forceinline__ uint32_t lm_bs(uint32_t base, int lane, int n0, int k0) {
    int mat = lane >> 3, r = lane & 7;
    int row = n0 + r + ((mat & 2) ? 8 : 0);
    int colb = (k0 + ((mat & 1) ? 8 : 0)) * 2;
    uint32_t off = (uint32_t)row * 128u + (uint32_t)colb;
    return base + SWZ(off);
}

// ---------------------------------------------------------------------------
// Convert + transpose W (512x512): Wt[n][k] = W[k][n], fp16 out.
// ---------------------------------------------------------------------------
__global__ __launch_bounds__(256) void convert_wt(
    const float* __restrict__ Wq, const float* __restrict__ Wkv)
{
    __shared__ float t[32][33];
    const float* W = blockIdx.z ? Wkv : Wq;
    __half* Wt = blockIdx.z ? g_Wkvt : g_Wqt;
    int k0 = blockIdx.x * 32, n0 = blockIdx.y * 32;
    int tx = threadIdx.x, ty = threadIdx.y;
    #pragma unroll
    for (int i = 0; i < 4; i++)
        t[ty + 8 * i][tx] = W[(size_t)(k0 + ty + 8 * i) * DIM + n0 + tx];
    __syncthreads();
    #pragma unroll
    for (int i = 0; i < 4; i++)
        Wt[(size_t)(n0 + ty + 8 * i) * DIM + k0 + tx] =
            __float2half(t[tx][ty + 8 * i]);
}

// ---------------------------------------------------------------------------
// Tensor-core projection GEMM: C(8192x512) = A(fp32) @ W + bias, fp16 out.
// Fused fp32->fp16 A conversion (LDG.128 -> cvt -> STS, reg double-buffered).
// Q output (blockIdx.z==0) is PRE-SCALED by EXC for the attention softmax.
// ---------------------------------------------------------------------------
#define GSM_A0 0
#define GSM_B0 16384
#define GSM_A1 32768
#define GSM_B1 49152
#define GEMM_SMEM 65536

__global__ __launch_bounds__(256) void gemm_tc(
    const float* __restrict__ M1, const float* __restrict__ M2,
    const float* __restrict__ bq, const float* __restrict__ bkv)
{
    extern __shared__ char smem[];
    const uint32_t sb = smem_u32(smem);

    const float* A32; const __half* Wt;
    const float* bias; __half* C;
    if (blockIdx.z == 0) { A32 = M1; Wt = g_Wqt;  bias = bq;  C = g_Qh;  }
    else                 { A32 = M2; Wt = g_Wkvt; bias = bkv; C = g_KVh; }
    const float escale = (blockIdx.z == 0) ? EXC : 1.0f;

    const int tid = threadIdx.x;
    const int lane = tid & 31, wid = tid >> 5;
    const int g = lane >> 2, tig = lane & 3;
    const int wm = wid & 1, wn = wid >> 1;
    const int m0 = blockIdx.y * 128, n0 = blockIdx.x * 128;

    const int lrow = tid >> 3, lch = tid & 7;

    const float* Ab = A32 + (size_t)(m0 + lrow) * DIM + lch * 8;
    uint32_t asw[4];
    #pragma unroll
    for (int p = 0; p < 4; p++)
        asw[p] = SWZ((uint32_t)(lrow + p * 32) * 128u + (uint32_t)lch * 16u);

    float4 pre[4][2];

    {
        const __half* Bs = Wt + (size_t)(n0 + lrow) * DIM + lch * 8;
        #pragma unroll
        for (int p = 0; p < 4; p++)
            CP_ASYNC16(sb + GSM_B0 + asw[p], Bs + (size_t)p * 32 * DIM);
        CP_COMMIT();
        #pragma unroll
        for (int p = 0; p < 4; p++) {
            pre[p][0] = *(const float4*)(Ab + (size_t)p * 32 * DIM);
            pre[p][1] = *(const float4*)(Ab + (size_t)p * 32 * DIM + 4);
        }
        #pragma unroll
        for (int p = 0; p < 4; p++) {
            uint4 w = make_uint4(cvt_h2(pre[p][0].y, pre[p][0].x),
                                 cvt_h2(pre[p][0].w, pre[p][0].z),
                                 cvt_h2(pre[p][1].y, pre[p][1].x),
                                 cvt_h2(pre[p][1].w, pre[p][1].z));
            *(uint4*)(smem + GSM_A0 + asw[p]) = w;
        }
        CP_WAIT0();
    }
    __syncthreads();

    float acc[4][4][4];
    #pragma unroll
    for (int m = 0; m < 4; m++)
        #pragma unroll
        for (int n = 0; n < 4; n++)
            #pragma unroll
            for (int k = 0; k < 4; k++) acc[m][n][k] = 0.f;

    for (int kt = 0; kt < 8; kt++) {
        const int cur = kt & 1, nxt = cur ^ 1;
        if (kt < 7) {
            const float* An = Ab + (kt + 1) * 64;
            #pragma unroll
            for (int p = 0; p < 4; p++) {
                pre[p][0] = *(const float4*)(An + (size_t)p * 32 * DIM);
                pre[p][1] = *(const float4*)(An + (size_t)p * 32 * DIM + 4);
            }
            const __half* Bs = Wt + (size_t)(n0 + lrow) * DIM + (kt + 1) * 64 + lch * 8;
            const uint32_t bb = sb + (nxt ? GSM_B1 : GSM_B0);
            #pragma unroll
            for (int p = 0; p < 4; p++)
                CP_ASYNC16(bb + asw[p], Bs + (size_t)p * 32 * DIM);
            CP_COMMIT();
        }

        const uint32_t abase = sb + (cur ? GSM_A1 : GSM_A0);
        const uint32_t bbase = sb + (cur ? GSM_B1 : GSM_B0);

        #pragma unroll
        for (int kf = 0; kf < 4; kf++) {
            uint32_t qa[4][4];
            #pragma unroll
            for (int m = 0; m < 4; m++)
                LDSM_X4(qa[m][0], qa[m][1], qa[m][2], qa[m][3],
                        lm_a(abase, lane, wm * 64 + m * 16, kf * 16));
            uint32_t bb[2][4];
            #pragma unroll
            for (int np = 0; np < 2; np++)
                LDSM_X4(bb[np][0], bb[np][1], bb[np][2], bb[np][3],
                        lm_bs(bbase, lane, wn * 32 + np * 16, kf * 16));
            #pragma unroll
            for (int m = 0; m < 4; m++)
                #pragma unroll
                for (int np = 0; np < 2; np++)
                    #pragma unroll
                    for (int nt = 0; nt < 2; nt++)
                        mma_f16(acc[m][np * 2 + nt],
                                qa[m][0], qa[m][1], qa[m][2], qa[m][3],
                                bb[np][nt * 2], bb[np][nt * 2 + 1]);
        }

        if (kt < 7) {
            const uint32_t ab = sb + (nxt ? GSM_A1 : GSM_A0);
            #pragma unroll
            for (int p = 0; p < 4; p++) {
                uint4 w = make_uint4(cvt_h2(pre[p][0].y, pre[p][0].x),
                                     cvt_h2(pre[p][0].w, pre[p][0].z),
                                     cvt_h2(pre[p][1].y, pre[p][1].x),
                                     cvt_h2(pre[p][1].w, pre[p][1].z));
                *(uint4*)(smem + (ab - sb) + asw[p]) = w;
            }
            CP_WAIT0();
        }
        __syncthreads();
    }

    float2 bf[4];
    #pragma unroll
    for (int n = 0; n < 4; n++)
        bf[n] = *(const float2*)&bias[n0 + wn * 32 + n * 8 + 2 * tig];

    #pragma unroll
    for (int m = 0; m < 4; m++) {
        int row = m0 + wm * 64 + m * 16 + g;
        #pragma unroll
        for (int n = 0; n < 4; n++) {
            int col = n0 + wn * 32 + n * 8 + 2 * tig;
            *(uint32_t*)(C + (size_t)row * DIM + col) =
                cvt_h2((acc[m][n][1] + bf[n].y) * escale,
                       (acc[m][n][0] + bf[n].x) * escale);
            *(uint32_t*)(C + (size_t)(row + 8) * DIM + col) =
                cvt_h2((acc[m][n][3] + bf[n].y) * escale,
                       (acc[m][n][2] + bf[n].x) * escale);
        }
    }
}

// ---------------------------------------------------------------------------
// fp16 mma.sync flash attention.  [R15 structure — unchanged]
// ---------------------------------------------------------------------------
#define QROWS 128
#define SMQ   0
#define SMK0  16384
#define SMM2  49152
#define ATT_SMEM (49152 + 2 * 128 * 4)
#define ONES_H2 0x3C003C00u

__global__ __launch_bounds__(128, 2) void attn_mma(
    const int* __restrict__ um1, const int* __restrict__ um2)
{
    extern __shared__ char smem[];
    const uint32_t sb = smem_u32(smem);
    float* m2f = (float*)(smem + SMM2);

    const int tid = threadIdx.x;
    const int lane = tid & 31, wid = tid >> 5;
    const int g = lane >> 2, tig = lane & 3;
    const int b = blockIdx.z, h = blockIdx.y, qt = blockIdx.x;
    const int mbase = wid * 32;

    {
        const __half* src = g_KVh + (size_t)(b * SEQ) * DIM + h * HD;
        #pragma unroll
        for (int p = 0; p < 8; p++) {
            int row = (tid >> 3) + p * 16, ch = tid & 7;
            uint32_t dst = sb + SMK0 + SWZ((uint32_t)row * 128u + (uint32_t)ch * 16u);
            CP_ASYNC16(dst, src + (size_t)row * DIM + ch * 8);
        }
        CP_COMMIT();
        m2f[tid] = (um2[b * SEQ + tid] != 0) ? 0.0f : -1e30f;

        const __half* qs = g_Qh + (size_t)(b * SEQ + qt * QROWS) * DIM + h * HD;
        #pragma unroll
        for (int p = 0; p < 8; p++) {
            int row = (tid >> 3) + p * 16, ch = tid & 7;
            uint4 v = *(const uint4*)(qs + (size_t)row * DIM + ch * 8);
            *(uint4*)(smem + SMQ + SWZ((uint32_t)row * 128u + (uint32_t)ch * 16u)) = v;
        }
    }

    bool rv[2][2];
    #pragma unroll
    for (int m = 0; m < 2; m++)
        #pragma unroll
        for (int r = 0; r < 2; r++)
            rv[m][r] = um1[b * SEQ + qt * QROWS + mbase + m * 16 + r * 8 + g] != 0;

    const int matq = lane >> 3, rl = lane & 7;
    const uint32_t rsw = (uint32_t)rl << 4;
    const uint32_t row_bs = (uint32_t)(rl + ((matq & 2) ? 8 : 0)) * 128u;
    const uint32_t cl_bs  = (matq & 1) ? 16u : 0u;
    uint32_t bsk[4];
    #pragma unroll
    for (int kf = 0; kf < 4; kf++)
        bsk[kf] = sb + SMK0 + row_bs + (((uint32_t)kf * 32u + cl_bs) ^ rsw);
    const uint32_t row_bo = (uint32_t)(rl + ((matq & 1) ? 8 : 0)) * 128u;
    const uint32_t cl_bo  = (matq & 2) ? 16u : 0u;
    uint32_t bok[4];
    #pragma unroll
    for (int dp = 0; dp < 4; dp++)
        bok[dp] = sb + SMK0 + row_bo + (((uint32_t)dp * 32u + cl_bo) ^ rsw);

    __syncthreads();   // Q visible

    uint32_t qa[2][4][4];
    #pragma unroll
    for (int m = 0; m < 2; m++)
        #pragma unroll
        for (int kf = 0; kf < 4; kf++)
            LDSM_X4(qa[m][kf][0], qa[m][kf][1], qa[m][kf][2], qa[m][kf][3],
                    lm_a(sb + SMQ, lane, mbase + m * 16, kf * 16));

    float oc[2][8][4];
    #pragma unroll
    for (int m = 0; m < 2; m++)
        #pragma unroll
        for (int n = 0; n < 8; n++)
            #pragma unroll
            for (int k = 0; k < 4; k++) oc[m][n][k] = 0.f;
    float os[2][4];
    #pragma unroll
    for (int m = 0; m < 2; m++)
        #pragma unroll
        for (int k = 0; k < 4; k++) os[m][k] = 0.f;

    for (int kt = 0; kt < 16; kt++) {
        const int cur = kt & 1, nxt = cur ^ 1;
        if (kt < 15) {
            const __half* src =
                g_KVh + (size_t)(b * SEQ + (kt + 1) * 128) * DIM + h * HD;
            #pragma unroll
            for (int p = 0; p < 8; p++) {
                int row = (tid >> 3) + p * 16, ch = tid & 7;
                uint32_t dst = sb + SMK0 + (uint32_t)nxt * 16384u +
                               SWZ((uint32_t)row * 128u + (uint32_t)ch * 16u);
                CP_ASYNC16(dst, src + (size_t)row * DIM + ch * 8);
            }
            CP_COMMIT();
            m2f[nxt * 128 + tid] = (um2[b * SEQ + (kt + 1) * 128 + tid] != 0) ? 0.0f : -1e30f;
            CP_WAIT1();
        } else {
            CP_WAIT0();
        }
        __syncthreads();   // K[cur] + m2[cur] ready

        const uint32_t koff = (uint32_t)cur * 16384u;
        uint32_t bsc[4], boc[4];
        #pragma unroll
        for (int i = 0; i < 4; i++) { bsc[i] = bsk[i] + koff; boc[i] = bok[i] + koff; }
        const float* m2c = m2f + cur * 128 + 2 * tig;

        #pragma unroll
        for (int c4 = 0; c4 < 4; c4++) {
            // ---- S chunk: 32 keys x 2 m-tiles (kf-outer) ----
            float sc[2][4][4];
            #pragma unroll
            for (int m = 0; m < 2; m++)
                #pragma unroll
                for (int n = 0; n < 4; n++)
                    #pragma unroll
                    for (int k = 0; k < 4; k++) sc[m][n][k] = 0.f;

            #pragma unroll
            for (int np = 0; np < 2; np++) {
                const uint32_t roff = (uint32_t)(c4 * 32 + np * 16) * 128u;
                uint32_t bb[4][4];
                #pragma unroll
                for (int kf = 0; kf < 4; kf++)
                    LDSM_X4(bb[kf][0], bb[kf][1], bb[kf][2], bb[kf][3],
                            bsc[kf] + roff);
                #pragma unroll
                for (int kf = 0; kf < 4; kf++)
                    #pragma unroll
                    for (int m = 0; m < 2; m++)
                        #pragma unroll
                        for (int nt = 0; nt < 2; nt++)
                            mma_f16(sc[m][np * 2 + nt],
                                    qa[m][kf][0], qa[m][kf][1], qa[m][kf][2], qa[m][kf][3],
                                    bb[kf][nt * 2], bb[kf][nt * 2 + 1]);
            }

            // ---- softmax: masked add -> f16x2 pack -> ex2.f16x2 ----
            uint32_t aP[2][2][4];
            #pragma unroll
            for (int m = 0; m < 2; m++) {
                #pragma unroll
                for (int n = 0; n < 4; n++) {
                    float2 mv = *(const float2*)&m2c[c4 * 32 + n * 8];
                    float x0 = sc[m][n][0] + mv.x;
                    float x1 = sc[m][n][1] + mv.y;
                    float x2 = sc[m][n][2] + mv.x;
                    float x3 = sc[m][n][3] + mv.y;
                    x0 = rv[m][0] ? x0 : 0.0f;
                    x1 = rv[m][0] ? x1 : 0.0f;
                    x2 = rv[m][1] ? x2 : 0.0f;
                    x3 = rv[m][1] ? x3 : 0.0f;
                    uint32_t plo = cvt_h2(x1, x0);
                    uint32_t phi = cvt_h2(x3, x2);
                    EX2_H2(plo, plo);
                    EX2_H2(phi, phi);
                    aP[m][n >> 1][(n & 1) * 2 + 0] = plo;
                    aP[m][n >> 1][(n & 1) * 2 + 1] = phi;
                }
            }

            // ---- O += P @ K (V = K); hoisted B-frag loads ----
            #pragma unroll
            for (int kf = 0; kf < 2; kf++) {
                const uint32_t roff = (uint32_t)(c4 * 32 + kf * 16) * 128u;
                uint32_t bo[4][4];
                #pragma unroll
                for (int dp = 0; dp < 4; dp++)
                    LDSM_X4T(bo[dp][0], bo[dp][1], bo[dp][2], bo[dp][3],
                             boc[dp] + roff);
                #pragma unroll
                for (int m = 0; m < 2; m++)
                    mma_f16(os[m], aP[m][kf][0], aP[m][kf][1],
                            aP[m][kf][2], aP[m][kf][3], ONES_H2, ONES_H2);
                #pragma unroll
                for (int dp = 0; dp < 4; dp++)
                    #pragma unroll
                    for (int m = 0; m < 2; m++) {
                        mma_f16(oc[m][dp * 2],
                                aP[m][kf][0], aP[m][kf][1], aP[m][kf][2], aP[m][kf][3],
                                bo[dp][0], bo[dp][1]);
                        mma_f16(oc[m][dp * 2 + 1],
                                aP[m][kf][0], aP[m][kf][1], aP[m][kf][2], aP[m][kf][3],
                                bo[dp][2], bo[dp][3]);
                    }
            }
        }
        __syncthreads();   // done reading K[cur] before overwrite
    }

    // ---- finalize (fp16 store) ----
    __half* Og = g_A + (size_t)(b * SEQ + qt * QROWS) * DIM + h * HD;
    #pragma unroll
    for (int m = 0; m < 2; m++) {
        const float inv0 = 1.0f / os[m][0];
        const float inv1 = 1.0f / os[m][2];
        int row0 = mbase + m * 16 + g;
        #pragma unroll
        for (int dt = 0; dt < 8; dt++) {
            int col = dt * 8 + 2 * tig;
            *(uint32_t*)(Og + (size_t)row0 * DIM + col) =
                cvt_h2(oc[m][dt][1] * inv0, oc[m][dt][0] * inv0);
            *(uint32_t*)(Og + (size_t)(row0 + 8) * DIM + col) =
                cvt_h2(oc[m][dt][3] * inv1, oc[m][dt][2] * inv1);
        }
    }
}

// ---------------------------------------------------------------------------
// Epilogue: x = LN1(attn + modal1); out = LN2(attn + x).
// WARP-PER-ROW: 8 warps/block, one 512-float row per warp, 16 elems/lane,
// both LN reductions are pure shfl trees — no smem, no __syncthreads.
// ---------------------------------------------------------------------------
__global__ __launch_bounds__(256) void epilogue_kernel(
    const float* __restrict__ modal1,
    const float* __restrict__ g1, const float* __restrict__ b1,
    const float* __restrict__ g2, const float* __restrict__ b2,
    float* __restrict__ out)
{
    const int row = blockIdx.x * 8 + (threadIdx.x >> 5);
    const int lane = threadIdx.x & 31;
    const size_t rbase = (size_t)row * DIM;

    float av[16], x[16];
    #pragma unroll
    for (int i = 0; i < 4; i++) {
        int col = i * 128 + lane * 4;
        uint2 ah = *(const uint2*)(g_A + rbase + col);
        float2 a01 = __half22float2(*(const __half2*)&ah.x);
        float2 a23 = __half22float2(*(const __half2*)&ah.y);
        float4 mv = *(const float4*)(modal1 + rbase + col);
        av[4*i+0] = a01.x; av[4*i+1] = a01.y; av[4*i+2] = a23.x; av[4*i+3] = a23.y;
        x[4*i+0] = a01.x + mv.x;
        x[4*i+1] = a01.y + mv.y;
        x[4*i+2] = a23.x + mv.z;
        x[4*i+3] = a23.y + mv.w;
    }

    float s = 0.f, q = 0.f;
    #pragma unroll
    for (int j = 0; j < 16; j++) { s += x[j]; q += x[j] * x[j]; }
    #pragma unroll
    for (int off = 16; off > 0; off >>= 1) {
        s += __shfl_xor_sync(0xffffffffu, s, off);
        q += __shfl_xor_sync(0xffffffffu, q, off);
    }
    float mean = s * (1.0f / 512.0f);
    float var  = q * (1.0f / 512.0f) - mean * mean;
    float rstd = rsqrtf(var + 1e-5f);

    float y[16];
    #pragma unroll
    for (int i = 0; i < 4; i++) {
        int col = i * 128 + lane * 4;
        float4 gf = *(const float4*)(g1 + col);
        float4 bf = *(const float4*)(b1 + col);
        y[4*i+0] = av[4*i+0] + ((x[4*i+0] - mean) * rstd * gf.x + bf.x);
        y[4*i+1] = av[4*i+1] + ((x[4*i+1] - mean) * rstd * gf.y + bf.y);
        y[4*i+2] = av[4*i+2] + ((x[4*i+2] - mean) * rstd * gf.z + bf.z);
        y[4*i+3] = av[4*i+3] + ((x[4*i+3] - mean) * rstd * gf.w + bf.w);
    }

    s = 0.f; q = 0.f;
    #pragma unroll
    for (int j = 0; j < 16; j++) { s += y[j]; q += y[j] * y[j]; }
    #pragma unroll
    for (int off = 16; off > 0; off >>= 1) {
        s += __shfl_xor_sync(0xffffffffu, s, off);
        q += __shfl_xor_sync(0xffffffffu, q, off);
    }
    float mean2 = s * (1.0f / 512.0f);
    float var2  = q * (1.0f / 512.0f) - mean2 * mean2;
    float rstd2 = rsqrtf(var2 + 1e-5f);

    #pragma unroll
    for (int i = 0; i < 4; i++) {
        int col = i * 128 + lane * 4;
        float4 gf = *(const float4*)(g2 + col);
        float4 bf = *(const float4*)(b2 + col);
        float4 ov = make_float4((y[4*i+0] - mean2) * rstd2 * gf.x + bf.x,
                                (y[4*i+1] - mean2) * rstd2 * gf.y + bf.y,
                                (y[4*i+2] - mean2) * rstd2 * gf.z + bf.z,
                                (y[4*i+3] - mean2) * rstd2 * gf.w + bf.w);
        *(float4*)(out + rbase + col) = ov;
    }
}

// ---------------------------------------------------------------------------
extern "C" void kernel_launch(void* const* d_in, const int* in_sizes, int n_in,
                              void* d_out, int out_size)
{
    const float* modal1 = (const float*)d_in[0];
    const float* modal2 = (const float*)d_in[1];
    const int*   um1    = (const int*)  d_in[2];
    const int*   um2    = (const int*)  d_in[3];
    const float* Wq     = (const float*)d_in[4];
    const float* bq     = (const float*)d_in[5];
    const float* Wkv    = (const float*)d_in[6];
    const float* bkv    = (const float*)d_in[7];
    const float* ln1g   = (const float*)d_in[8];
    const float* ln1b   = (const float*)d_in[9];
    // d_in[10..13] = W1,b1,W2,b2 -> FFN output is discarded by the reference.
    const float* ln2g   = (const float*)d_in[14];
    const float* ln2b   = (const float*)d_in[15];
    float* out = (float*)d_out;

    cudaFuncSetAttribute(gemm_tc,
                         cudaFuncAttributeMaxDynamicSharedMemorySize, GEMM_SMEM);
    cudaFuncSetAttribute(attn_mma,
                         cudaFuncAttributeMaxDynamicSharedMemorySize, ATT_SMEM);

    dim3 gw(16, 16, 2);
    convert_wt<<<gw, dim3(32, 8)>>>(Wq, Wkv);

    dim3 gg(DIM / 128, (BSZ * SEQ) / 128, 2);
    gemm_tc<<<gg, 256, GEMM_SMEM>>>(modal1, modal2, bq, bkv);

    dim3 ga(SEQ / QROWS, NHEAD, BSZ);
    attn_mma<<<ga, 128, ATT_SMEM>>>(um1, um2);

    epilogue_kernel<<<BSZ * SEQ / 8, 256>>>(modal1, ln1g, ln1b, ln2g, ln2b, out);
}

// round 17
// speedup vs baseline: 1.1460x; 1.0048x over previous
#include <cuda_runtime.h>
#include <cuda_fp16.h>
#include <cstdint>
#include <math.h>

#define BSZ 4
#define SEQ 2048
#define DIM 512
#define NHEAD 8
#define HD 64
#define ATT_SCALE 0.044194173824159216f        // 1/sqrt(512)
#define EXC (ATT_SCALE * 1.4426950408889634f)  // scale * log2(e)

// ---------------------------------------------------------------------------
// Scratch (static device globals: allocation-free)
// ---------------------------------------------------------------------------
__device__ __half g_Wqt [DIM*DIM];   // transposed [n][k]
__device__ __half g_Wkvt[DIM*DIM];   // transposed [n][k]
__device__ __half g_Qh [BSZ*SEQ*DIM];   // pre-scaled by EXC
__device__ __half g_KVh[BSZ*SEQ*DIM];
__device__ __half g_A  [BSZ*SEQ*DIM];   // attention output, fp16

// ---------------------------------------------------------------------------
// Baseline-PTX helpers (compute_80 features only: mma.sync / ldmatrix / cp.async)
// ---------------------------------------------------------------------------
__device__ __forceinline__ uint32_t smem_u32(const void* p) {
    uint32_t a;
    asm("{ .reg .u64 t; cvta.to.shared.u64 t, %1; cvt.u32.u64 %0, t; }" : "=r"(a) : "l"(p));
    return a;
}
#define SWZ(off) ((off) ^ (((off) >> 3) & 0x70))

#define LDSM_X4(r0,r1,r2,r3,a) \
    asm volatile("ldmatrix.sync.aligned.m8n8.x4.shared.b16 {%0,%1,%2,%3}, [%4];" \
        : "=r"(r0),"=r"(r1),"=r"(r2),"=r"(r3) : "r"(a))
#define LDSM_X4T(r0,r1,r2,r3,a) \
    asm volatile("ldmatrix.sync.aligned.m8n8.x4.trans.shared.b16 {%0,%1,%2,%3}, [%4];" \
        : "=r"(r0),"=r"(r1),"=r"(r2),"=r"(r3) : "r"(a))

__device__ __forceinline__ void mma_f16(float c[4], uint32_t a0, uint32_t a1,
                                        uint32_t a2, uint32_t a3,
                                        uint32_t b0, uint32_t b1) {
    asm volatile(
        "mma.sync.aligned.m16n8k16.row.col.f32.f16.f16.f32 "
        "{%0,%1,%2,%3}, {%4,%5,%6,%7}, {%8,%9}, {%0,%1,%2,%3};"
        : "+f"(c[0]), "+f"(c[1]), "+f"(c[2]), "+f"(c[3])
        : "r"(a0), "r"(a1), "r"(a2), "r"(a3), "r"(b0), "r"(b1));
}

#define CP_ASYNC16(dst, src) \
    asm volatile("cp.async.cg.shared.global [%0], [%1], 16;" :: "r"(dst), "l"(src))
#define CP_COMMIT() asm volatile("cp.async.commit_group;" ::: "memory")
#define CP_WAIT1()  asm volatile("cp.async.wait_group 1;" ::: "memory")
#define CP_WAIT0()  asm volatile("cp.async.wait_group 0;" ::: "memory")

__device__ __forceinline__ uint32_t cvt_h2(float hi, float lo) {
    uint32_t r;
    asm("cvt.rn.f16x2.f32 %0, %1, %2;" : "=r"(r) : "f"(hi), "f"(lo));
    return r;
}
#define EX2_H2(d, a) asm("ex2.approx.f16x2 %0, %1;" : "=r"(d) : "r"(a))

// ldmatrix address builders (row stride 128B, SW128 swizzle) — prologue only
__device__ __forceinline__ uint32_t lm_a(uint32_t base, int lane, int m0, int k0) {
    int mat = lane >> 3, r = lane & 7;
    int row = m0 + r + ((mat & 1) ? 8 : 0);
    int colb = (k0 + ((mat & 2) ? 8 : 0)) * 2;
    uint32_t off = (uint32_t)row * 128u + (uint32_t)colb;
    return base + SWZ(off);
}
__device__ __forceinline__ uint32_t lm_bs(uint32_t base, int lane, int n0, int k0) {
    int mat = lane >> 3, r = lane & 7;
    int row = n0 + r + ((mat & 2) ? 8 : 0);
    int colb = (k0 + ((mat & 1) ? 8 : 0)) * 2;
    uint32_t off = (uint32_t)row * 128u + (uint32_t)colb;
    return base + SWZ(off);
}

// ---------------------------------------------------------------------------
// Convert + transpose W (512x512): Wt[n][k] = W[k][n], fp16 out.
// ---------------------------------------------------------------------------
__global__ __launch_bounds__(256) void convert_wt(
    const float* __restrict__ Wq, const float* __restrict__ Wkv)
{
    __shared__ float t[32][33];
    const float* W = blockIdx.z ? Wkv : Wq;
    __half* Wt = blockIdx.z ? g_Wkvt : g_Wqt;
    int k0 = blockIdx.x * 32, n0 = blockIdx.y * 32;
    int tx = threadIdx.x, ty = threadIdx.y;
    #pragma unroll
    for (int i = 0; i < 4; i++)
        t[ty + 8 * i][tx] = W[(size_t)(k0 + ty + 8 * i) * DIM + n0 + tx];
    __syncthreads();
    #pragma unroll
    for (int i = 0; i < 4; i++)
        Wt[(size_t)(n0 + ty + 8 * i) * DIM + k0 + tx] =
            __float2half(t[tx][ty + 8 * i]);
}

// ---------------------------------------------------------------------------
// Tensor-core projection GEMM: C(8192x512) = A(fp32) @ W + bias, fp16 out.
// Fused fp32->fp16 A conversion. Q pre-scaled by EXC.  [R15 — unchanged]
// ---------------------------------------------------------------------------
#define GSM_A0 0
#define GSM_B0 16384
#define GSM_A1 32768
#define GSM_B1 49152
#define GEMM_SMEM 65536

__global__ __launch_bounds__(256) void gemm_tc(
    const float* __restrict__ M1, const float* __restrict__ M2,
    const float* __restrict__ bq, const float* __restrict__ bkv)
{
    extern __shared__ char smem[];
    const uint32_t sb = smem_u32(smem);

    const float* A32; const __half* Wt;
    const float* bias; __half* C;
    if (blockIdx.z == 0) { A32 = M1; Wt = g_Wqt;  bias = bq;  C = g_Qh;  }
    else                 { A32 = M2; Wt = g_Wkvt; bias = bkv; C = g_KVh; }
    const float escale = (blockIdx.z == 0) ? EXC : 1.0f;

    const int tid = threadIdx.x;
    const int lane = tid & 31, wid = tid >> 5;
    const int g = lane >> 2, tig = lane & 3;
    const int wm = wid & 1, wn = wid >> 1;
    const int m0 = blockIdx.y * 128, n0 = blockIdx.x * 128;

    const int lrow = tid >> 3, lch = tid & 7;

    const float* Ab = A32 + (size_t)(m0 + lrow) * DIM + lch * 8;
    uint32_t asw[4];
    #pragma unroll
    for (int p = 0; p < 4; p++)
        asw[p] = SWZ((uint32_t)(lrow + p * 32) * 128u + (uint32_t)lch * 16u);

    float4 pre[4][2];

    {
        const __half* Bs = Wt + (size_t)(n0 + lrow) * DIM + lch * 8;
        #pragma unroll
        for (int p = 0; p < 4; p++)
            CP_ASYNC16(sb + GSM_B0 + asw[p], Bs + (size_t)p * 32 * DIM);
        CP_COMMIT();
        #pragma unroll
        for (int p = 0; p < 4; p++) {
            pre[p][0] = *(const float4*)(Ab + (size_t)p * 32 * DIM);
            pre[p][1] = *(const float4*)(Ab + (size_t)p * 32 * DIM + 4);
        }
        #pragma unroll
        for (int p = 0; p < 4; p++) {
            uint4 w = make_uint4(cvt_h2(pre[p][0].y, pre[p][0].x),
                                 cvt_h2(pre[p][0].w, pre[p][0].z),
                                 cvt_h2(pre[p][1].y, pre[p][1].x),
                                 cvt_h2(pre[p][1].w, pre[p][1].z));
            *(uint4*)(smem + GSM_A0 + asw[p]) = w;
        }
        CP_WAIT0();
    }
    __syncthreads();

    float acc[4][4][4];
    #pragma unroll
    for (int m = 0; m < 4; m++)
        #pragma unroll
        for (int n = 0; n < 4; n++)
            #pragma unroll
            for (int k = 0; k < 4; k++) acc[m][n][k] = 0.f;

    for (int kt = 0; kt < 8; kt++) {
        const int cur = kt & 1, nxt = cur ^ 1;
        if (kt < 7) {
            const float* An = Ab + (kt + 1) * 64;
            #pragma unroll
            for (int p = 0; p < 4; p++) {
                pre[p][0] = *(const float4*)(An + (size_t)p * 32 * DIM);
                pre[p][1] = *(const float4*)(An + (size_t)p * 32 * DIM + 4);
            }
            const __half* Bs = Wt + (size_t)(n0 + lrow) * DIM + (kt + 1) * 64 + lch * 8;
            const uint32_t bb = sb + (nxt ? GSM_B1 : GSM_B0);
            #pragma unroll
            for (int p = 0; p < 4; p++)
                CP_ASYNC16(bb + asw[p], Bs + (size_t)p * 32 * DIM);
            CP_COMMIT();
        }

        const uint32_t abase = sb + (cur ? GSM_A1 : GSM_A0);
        const uint32_t bbase = sb + (cur ? GSM_B1 : GSM_B0);

        #pragma unroll
        for (int kf = 0; kf < 4; kf++) {
            uint32_t qa[4][4];
            #pragma unroll
            for (int m = 0; m < 4; m++)
                LDSM_X4(qa[m][0], qa[m][1], qa[m][2], qa[m][3],
                        lm_a(abase, lane, wm * 64 + m * 16, kf * 16));
            uint32_t bb[2][4];
            #pragma unroll
            for (int np = 0; np < 2; np++)
                LDSM_X4(bb[np][0], bb[np][1], bb[np][2], bb[np][3],
                        lm_bs(bbase, lane, wn * 32 + np * 16, kf * 16));
            #pragma unroll
            for (int m = 0; m < 4; m++)
                #pragma unroll
                for (int np = 0; np < 2; np++)
                    #pragma unroll
                    for (int nt = 0; nt < 2; nt++)
                        mma_f16(acc[m][np * 2 + nt],
                                qa[m][0], qa[m][1], qa[m][2], qa[m][3],
                                bb[np][nt * 2], bb[np][nt * 2 + 1]);
        }

        if (kt < 7) {
            const uint32_t ab = sb + (nxt ? GSM_A1 : GSM_A0);
            #pragma unroll
            for (int p = 0; p < 4; p++) {
                uint4 w = make_uint4(cvt_h2(pre[p][0].y, pre[p][0].x),
                                     cvt_h2(pre[p][0].w, pre[p][0].z),
                                     cvt_h2(pre[p][1].y, pre[p][1].x),
                                     cvt_h2(pre[p][1].w, pre[p][1].z));
                *(uint4*)(smem + (ab - sb) + asw[p]) = w;
            }
            CP_WAIT0();
        }
        __syncthreads();
    }

    float2 bf[4];
    #pragma unroll
    for (int n = 0; n < 4; n++)
        bf[n] = *(const float2*)&bias[n0 + wn * 32 + n * 8 + 2 * tig];

    #pragma unroll
    for (int m = 0; m < 4; m++) {
        int row = m0 + wm * 64 + m * 16 + g;
        #pragma unroll
        for (int n = 0; n < 4; n++) {
            int col = n0 + wn * 32 + n * 8 + 2 * tig;
            *(uint32_t*)(C + (size_t)row * DIM + col) =
                cvt_h2((acc[m][n][1] + bf[n].y) * escale,
                       (acc[m][n][0] + bf[n].x) * escale);
            *(uint32_t*)(C + (size_t)(row + 8) * DIM + col) =
                cvt_h2((acc[m][n][3] + bf[n].y) * escale,
                       (acc[m][n][2] + bf[n].x) * escale);
        }
    }
}

// ---------------------------------------------------------------------------
// fp16 mma.sync flash attention.
// 128 threads / 4 warps, 32 q-rows/warp, 2 CTAs/SM.
// THIS ROUND: 3-buffer K ring (Q staging region reused as buffer 2) with ONE
// __syncthreads per k-tile (was 2): wait_group 1 -> sync -> issue K[kt+2]
// into buf[(kt+2)%3] (free since iter kt-1) -> compute buf[kt%3].
// ---------------------------------------------------------------------------
#define QROWS 128
#define SMB2  0               // buffer 2 (Q staging in prologue)
#define SMB0  16384
#define SMB1  32768
#define SMM2  49152           // 3 x 128 floats
#define ATT_SMEM (49152 + 3 * 128 * 4)
#define ONES_H2 0x3C003C00u

__global__ __launch_bounds__(128, 2) void attn_mma(
    const int* __restrict__ um1, const int* __restrict__ um2)
{
    extern __shared__ char smem[];
    const uint32_t sb = smem_u32(smem);
    float* m2f = (float*)(smem + SMM2);

    const int tid = threadIdx.x;
    const int lane = tid & 31, wid = tid >> 5;
    const int g = lane >> 2, tig = lane & 3;
    const int b = blockIdx.z, h = blockIdx.y, qt = blockIdx.x;
    const int mbase = wid * 32;

    const int krow = tid >> 3, kch = tid & 7;
    uint32_t ksw[8];
    #pragma unroll
    for (int p = 0; p < 8; p++)
        ksw[p] = SWZ((uint32_t)(krow + p * 16) * 128u + (uint32_t)kch * 16u);
    const __half* Kb = g_KVh + (size_t)(b * SEQ + krow) * DIM + h * HD + kch * 8;

    // --- prologue: Q -> buf2 region (plain stores); K0 -> buf0, K1 -> buf1 ---
    {
        #pragma unroll
        for (int p = 0; p < 8; p++)
            CP_ASYNC16(sb + SMB0 + ksw[p], Kb + (size_t)p * 16 * DIM);
        CP_COMMIT();
        #pragma unroll
        for (int p = 0; p < 8; p++)
            CP_ASYNC16(sb + SMB1 + ksw[p], Kb + (size_t)(128 + p * 16) * DIM);
        CP_COMMIT();
        m2f[tid]       = (um2[b * SEQ + tid] != 0) ? 0.0f : -1e30f;
        m2f[128 + tid] = (um2[b * SEQ + 128 + tid] != 0) ? 0.0f : -1e30f;

        const __half* qs = g_Qh + (size_t)(b * SEQ + qt * QROWS) * DIM + h * HD;
        #pragma unroll
        for (int p = 0; p < 8; p++) {
            int row = krow + p * 16;
            uint4 v = *(const uint4*)(qs + (size_t)row * DIM + kch * 8);
            *(uint4*)(smem + SMB2 + SWZ((uint32_t)row * 128u + (uint32_t)kch * 16u)) = v;
        }
    }

    bool rv[2][2];
    #pragma unroll
    for (int m = 0; m < 2; m++)
        #pragma unroll
        for (int r = 0; r < 2; r++)
            rv[m][r] = um1[b * SEQ + qt * QROWS + mbase + m * 16 + r * 8 + g] != 0;

    // --- precomputed LDSM lane bases, buffer-relative ---
    const int matq = lane >> 3, rl = lane & 7;
    const uint32_t rsw = (uint32_t)rl << 4;
    const uint32_t row_bs = (uint32_t)(rl + ((matq & 2) ? 8 : 0)) * 128u;
    const uint32_t cl_bs  = (matq & 1) ? 16u : 0u;
    uint32_t bsk[4];
    #pragma unroll
    for (int kf = 0; kf < 4; kf++)
        bsk[kf] = sb + row_bs + (((uint32_t)kf * 32u + cl_bs) ^ rsw);
    const uint32_t row_bo = (uint32_t)(rl + ((matq & 1) ? 8 : 0)) * 128u;
    const uint32_t cl_bo  = (matq & 2) ? 16u : 0u;
    uint32_t bok[4];
    #pragma unroll
    for (int dp = 0; dp < 4; dp++)
        bok[dp] = sb + row_bo + (((uint32_t)dp * 32u + cl_bo) ^ rsw);

    __syncthreads();   // Q + m2[0..1] visible

    // Q a-frags (persistent), read from buf2 region BEFORE it becomes a K buffer
    uint32_t qa[2][4][4];
    #pragma unroll
    for (int m = 0; m < 2; m++)
        #pragma unroll
        for (int kf = 0; kf < 4; kf++)
            LDSM_X4(qa[m][kf][0], qa[m][kf][1], qa[m][kf][2], qa[m][kf][3],
                    lm_a(sb + SMB2, lane, mbase + m * 16, kf * 16));

    float oc[2][8][4];
    #pragma unroll
    for (int m = 0; m < 2; m++)
        #pragma unroll
        for (int n = 0; n < 8; n++)
            #pragma unroll
            for (int k = 0; k < 4; k++) oc[m][n][k] = 0.f;
    float os[2][4];
    #pragma unroll
    for (int m = 0; m < 2; m++)
        #pragma unroll
        for (int k = 0; k < 4; k++) os[m][k] = 0.f;

    // rotating buffer bases: cur = kt%3, issue target = (kt+2)%3
    uint32_t bcur = SMB0, bnxt = SMB1, bnxt2 = SMB2;
    int mcur = 0, mnxt = 1, mnxt2 = 2;

    for (int kt = 0; kt < 16; kt++) {
        if (kt < 15) CP_WAIT1(); else CP_WAIT0();
        __syncthreads();   // K[kt] visible everywhere; buf[(kt+2)%3] fully drained

        if (kt + 2 < 16) {
            const __half* src = Kb + (size_t)(kt + 2) * 128 * DIM;
            #pragma unroll
            for (int p = 0; p < 8; p++)
                CP_ASYNC16(sb + bnxt2 + ksw[p], src + (size_t)p * 16 * DIM);
            CP_COMMIT();
            m2f[mnxt2 * 128 + tid] =
                (um2[b * SEQ + (kt + 2) * 128 + tid] != 0) ? 0.0f : -1e30f;
        }

        uint32_t bsc[4], boc[4];
        #pragma unroll
        for (int i = 0; i < 4; i++) { bsc[i] = bsk[i] + bcur; boc[i] = bok[i] + bcur; }
        const float* m2c = m2f + mcur * 128 + 2 * tig;

        #pragma unroll
        for (int c4 = 0; c4 < 4; c4++) {
            // ---- S chunk: 32 keys x 2 m-tiles (kf-outer) ----
            float sc[2][4][4];
            #pragma unroll
            for (int m = 0; m < 2; m++)
                #pragma unroll
                for (int n = 0; n < 4; n++)
                    #pragma unroll
                    for (int k = 0; k < 4; k++) sc[m][n][k] = 0.f;

            #pragma unroll
            for (int np = 0; np < 2; np++) {
                const uint32_t roff = (uint32_t)(c4 * 32 + np * 16) * 128u;
                uint32_t bb[4][4];
                #pragma unroll
                for (int kf = 0; kf < 4; kf++)
                    LDSM_X4(bb[kf][0], bb[kf][1], bb[kf][2], bb[kf][3],
                            bsc[kf] + roff);
                #pragma unroll
                for (int kf = 0; kf < 4; kf++)
                    #pragma unroll
                    for (int m = 0; m < 2; m++)
                        #pragma unroll
                        for (int nt = 0; nt < 2; nt++)
                            mma_f16(sc[m][np * 2 + nt],
                                    qa[m][kf][0], qa[m][kf][1], qa[m][kf][2], qa[m][kf][3],
                                    bb[kf][nt * 2], bb[kf][nt * 2 + 1]);
            }

            // ---- softmax: masked add -> f16x2 pack -> ex2.f16x2 ----
            uint32_t aP[2][2][4];
            #pragma unroll
            for (int m = 0; m < 2; m++) {
                #pragma unroll
                for (int n = 0; n < 4; n++) {
                    float2 mv = *(const float2*)&m2c[c4 * 32 + n * 8];
                    float x0 = sc[m][n][0] + mv.x;
                    float x1 = sc[m][n][1] + mv.y;
                    float x2 = sc[m][n][2] + mv.x;
                    float x3 = sc[m][n][3] + mv.y;
                    x0 = rv[m][0] ? x0 : 0.0f;
                    x1 = rv[m][0] ? x1 : 0.0f;
                    x2 = rv[m][1] ? x2 : 0.0f;
                    x3 = rv[m][1] ? x3 : 0.0f;
                    uint32_t plo = cvt_h2(x1, x0);
                    uint32_t phi = cvt_h2(x3, x2);
                    EX2_H2(plo, plo);
                    EX2_H2(phi, phi);
                    aP[m][n >> 1][(n & 1) * 2 + 0] = plo;
                    aP[m][n >> 1][(n & 1) * 2 + 1] = phi;
                }
            }

            // ---- O += P @ K (V = K); hoisted B-frag loads ----
            #pragma unroll
            for (int kf = 0; kf < 2; kf++) {
                const uint32_t roff = (uint32_t)(c4 * 32 + kf * 16) * 128u;
                uint32_t bo[4][4];
                #pragma unroll
                for (int dp = 0; dp < 4; dp++)
                    LDSM_X4T(bo[dp][0], bo[dp][1], bo[dp][2], bo[dp][3],
                             boc[dp] + roff);
                #pragma unroll
                for (int m = 0; m < 2; m++)
                    mma_f16(os[m], aP[m][kf][0], aP[m][kf][1],
                            aP[m][kf][2], aP[m][kf][3], ONES_H2, ONES_H2);
                #pragma unroll
                for (int dp = 0; dp < 4; dp++)
                    #pragma unroll
                    for (int m = 0; m < 2; m++) {
                        mma_f16(oc[m][dp * 2],
                                aP[m][kf][0], aP[m][kf][1], aP[m][kf][2], aP[m][kf][3],
                                bo[dp][0], bo[dp][1]);
                        mma_f16(oc[m][dp * 2 + 1],
                                aP[m][kf][0], aP[m][kf][1], aP[m][kf][2], aP[m][kf][3],
                                bo[dp][2], bo[dp][3]);
                    }
            }
        }

        // rotate ring
        uint32_t bt = bcur; bcur = bnxt; bnxt = bnxt2; bnxt2 = bt;
        int mt = mcur; mcur = mnxt; mnxt = mnxt2; mnxt2 = mt;
    }

    // ---- finalize (fp16 store) ----
    __half* Og = g_A + (size_t)(b * SEQ + qt * QROWS) * DIM + h * HD;
    #pragma unroll
    for (int m = 0; m < 2; m++) {
        const float inv0 = 1.0f / os[m][0];
        const float inv1 = 1.0f / os[m][2];
        int row0 = mbase + m * 16 + g;
        #pragma unroll
        for (int dt = 0; dt < 8; dt++) {
            int col = dt * 8 + 2 * tig;
            *(uint32_t*)(Og + (size_t)row0 * DIM + col) =
                cvt_h2(oc[m][dt][1] * inv0, oc[m][dt][0] * inv0);
            *(uint32_t*)(Og + (size_t)(row0 + 8) * DIM + col) =
                cvt_h2(oc[m][dt][3] * inv1, oc[m][dt][2] * inv1);
        }
    }
}

// ---------------------------------------------------------------------------
// Epilogue: warp-per-row, no smem, no barriers.  [R16 — unchanged]
// ---------------------------------------------------------------------------
__global__ __launch_bounds__(256) void epilogue_kernel(
    const float* __restrict__ modal1,
    const float* __restrict__ g1, const float* __restrict__ b1,
    const float* __restrict__ g2, const float* __restrict__ b2,
    float* __restrict__ out)
{
    const int row = blockIdx.x * 8 + (threadIdx.x >> 5);
    const int lane = threadIdx.x & 31;
    const size_t rbase = (size_t)row * DIM;

    float av[16], x[16];
    #pragma unroll
    for (int i = 0; i < 4; i++) {
        int col = i * 128 + lane * 4;
        uint2 ah = *(const uint2*)(g_A + rbase + col);
        float2 a01 = __half22float2(*(const __half2*)&ah.x);
        float2 a23 = __half22float2(*(const __half2*)&ah.y);
        float4 mv = *(const float4*)(modal1 + rbase + col);
        av[4*i+0] = a01.x; av[4*i+1] = a01.y; av[4*i+2] = a23.x; av[4*i+3] = a23.y;
        x[4*i+0] = a01.x + mv.x;
        x[4*i+1] = a01.y + mv.y;
        x[4*i+2] = a23.x + mv.z;
        x[4*i+3] = a23.y + mv.w;
    }

    float s = 0.f, q = 0.f;
    #pragma unroll
    for (int j = 0; j < 16; j++) { s += x[j]; q += x[j] * x[j]; }
    #pragma unroll
    for (int off = 16; off > 0; off >>= 1) {
        s += __shfl_xor_sync(0xffffffffu, s, off);
        q += __shfl_xor_sync(0xffffffffu, q, off);
    }
    float mean = s * (1.0f / 512.0f);
    float var  = q * (1.0f / 512.0f) - mean * mean;
    float rstd = rsqrtf(var + 1e-5f);

    float y[16];
    #pragma unroll
    for (int i = 0; i < 4; i++) {
        int col = i * 128 + lane * 4;
        float4 gf = *(const float4*)(g1 + col);
        float4 bf = *(const float4*)(b1 + col);
        y[4*i+0] = av[4*i+0] + ((x[4*i+0] - mean) * rstd * gf.x + bf.x);
        y[4*i+1] = av[4*i+1] + ((x[4*i+1] - mean) * rstd * gf.y + bf.y);
        y[4*i+2] = av[4*i+2] + ((x[4*i+2] - mean) * rstd * gf.z + bf.z);
        y[4*i+3] = av[4*i+3] + ((x[4*i+3] - mean) * rstd * gf.w + bf.w);
    }

    s = 0.f; q = 0.f;
    #pragma unroll
    for (int j = 0; j < 16; j++) { s += y[j]; q += y[j] * y[j]; }
    #pragma unroll
    for (int off = 16; off > 0; off >>= 1) {
        s += __shfl_xor_sync(0xffffffffu, s, off);
        q += __shfl_xor_sync(0xffffffffu, q, off);
    }
    float mean2 = s * (1.0f / 512.0f);
    float var2  = q * (1.0f / 512.0f) - mean2 * mean2;
    float rstd2 = rsqrtf(var2 + 1e-5f);

    #pragma unroll
    for (int i = 0; i < 4; i++) {
        int col = i * 128 + lane * 4;
        float4 gf = *(const float4*)(g2 + col);
        float4 bf = *(const float4*)(b2 + col);
        float4 ov = make_float4((y[4*i+0] - mean2) * rstd2 * gf.x + bf.x,
                                (y[4*i+1] - mean2) * rstd2 * gf.y + bf.y,
                                (y[4*i+2] - mean2) * rstd2 * gf.z + bf.z,
                                (y[4*i+3] - mean2) * rstd2 * gf.w + bf.w);
        *(float4*)(out + rbase + col) = ov;
    }
}

// ---------------------------------------------------------------------------
extern "C" void kernel_launch(void* const* d_in, const int* in_sizes, int n_in,
                              void* d_out, int out_size)
{
    const float* modal1 = (const float*)d_in[0];
    const float* modal2 = (const float*)d_in[1];
    const int*   um1    = (const int*)  d_in[2];
    const int*   um2    = (const int*)  d_in[3];
    const float* Wq     = (const float*)d_in[4];
    const float* bq     = (const float*)d_in[5];
    const float* Wkv    = (const float*)d_in[6];
    const float* bkv    = (const float*)d_in[7];
    const float* ln1g   = (const float*)d_in[8];
    const float* ln1b   = (const float*)d_in[9];
    // d_in[10..13] = W1,b1,W2,b2 -> FFN output is discarded by the reference.
    const float* ln2g   = (const float*)d_in[14];
    const float* ln2b   = (const float*)d_in[15];
    float* out = (float*)d_out;

    cudaFuncSetAttribute(gemm_tc,
                         cudaFuncAttributeMaxDynamicSharedMemorySize, GEMM_SMEM);
    cudaFuncSetAttribute(attn_mma,
                         cudaFuncAttributeMaxDynamicSharedMemorySize, ATT_SMEM);

    dim3 gw(16, 16, 2);
    convert_wt<<<gw, dim3(32, 8)>>>(Wq, Wkv);

    dim3 gg(DIM / 128, (BSZ * SEQ) / 128, 2);
    gemm_tc<<<gg, 256, GEMM_SMEM>>>(modal1, modal2, bq, bkv);

    dim3 ga(SEQ / QROWS, NHEAD, BSZ);
    attn_mma<<<ga, 128, ATT_SMEM>>>(um1, um2);

    epilogue_kernel<<<BSZ * SEQ / 8, 256>>>(modal1, ln1g, ln1b, ln2g, ln2b, out);
}